// round 14
// baseline (speedup 1.0000x reference)
#include <cuda_runtime.h>
#include <cuda_fp16.h>
#include <cstdint>

typedef long long ll;

#define NB 256
#define NS 32
#define ND 512
#define NHW 196
#define NM (NB*NHW)   // 50176

// --------------------- scratch layout (BYTE offsets) ----------------------
#define B_Q      ((ll)0)
#define B_PA     ((ll)524288)
#define B_CQ     ((ll)1048576)
#define B_PMP    ((ll)1572864)
#define B_PMF    ((ll)2097152)
#define B_PMC    ((ll)2621440)
#define B_V      ((ll)3145728)
#define B_U      ((ll)3670016)
#define B_READ   ((ll)4194304)
#define B_BIAS2  ((ll)4719616)
#define B_LOGIT  ((ll)4721664)
#define B_AR     ((ll)4922368)
#define B_WKT    ((ll)5242880)
#define B_W1AT   ((ll)6291456)
#define B_WKWT   ((ll)7340032)
#define B_WSCT   ((ll)8388608)
#define B_WPT    ((ll)10485760)
#define B_WCQT   ((ll)11534336)
#define B_WMT    ((ll)13631488)
#define B_WC1CT  ((ll)14680064)
#define B_NMBT   ((ll)15728640)
#define B_W1BT   ((ll)17825792)
#define B_QR     ((ll)18874368)
#define B_C0R    ((ll)19922944)
#define B_M0R    ((ll)20447232)
#define B_WC2R   ((ll)20971520)
#define B_KNOWT  ((ll)22020096)    // hi-ONLY plane E=25690112
#define B_SPK    ((ll)124780544)   // hi-ONLY plane E=25690112
#define B_WKP    ((ll)227540992)
#define B_QF     ((ll)228589568)
#define B_TOTAL  ((ll)229113856)

__device__ __align__(1024) char g_s[B_TOTAL];

// ===================== arch-generic PTX helpers ============================
__device__ __forceinline__ uint32_t smem_u32(const void* p) {
    uint32_t a;
    asm("{ .reg .u64 t; cvta.to.shared.u64 t, %1; cvt.u32.u64 %0, t; }"
        : "=r"(a) : "l"(p));
    return a;
}

#define MBARRIER_INIT(addr, cnt) \
    asm volatile("mbarrier.init.shared.b64 [%0], %1;" :: "r"(addr), "r"(cnt) : "memory")
#define MBARRIER_ARRIVE(addr) \
    asm volatile("mbarrier.arrive.shared.b64 _, [%0];" :: "r"(addr) : "memory")
#define MBARRIER_EXPECT_TX(addr, bytes) \
    asm volatile("mbarrier.arrive.expect_tx.shared.b64 _, [%0], %1;" \
                 :: "r"(addr), "r"(bytes) : "memory")
#define MBARRIER_WAIT_PARITY(addr, par) do { \
    uint32_t _m = (addr), _p = (par), _d; \
    asm volatile("{ .reg .pred p; mbarrier.try_wait.parity.acquire.cta.shared::cta.b64 p, [%1], %2;" \
                 " selp.b32 %0,1,0,p; }" : "=r"(_d) : "r"(_m), "r"(_p) : "memory"); \
    if (!_d) { \
        asm volatile("{ .reg .pred P1; WL_%=:" \
                     " mbarrier.try_wait.parity.acquire.cta.shared::cta.b64 P1, [%0], %1, 0x989680;" \
                     " @P1 bra.uni WD_%=; bra.uni WL_%=; WD_%=: }" \
                     :: "r"(_m), "r"(_p) : "memory"); \
    } \
} while (0)
#define FENCE_ASYNC() asm volatile("fence.proxy.async.shared::cta;" ::: "memory")

#define BULK_G2S(dst, src, bytes, mbar) \
    asm volatile("cp.async.bulk.shared::cluster.global.mbarrier::complete_tx::bytes " \
                 "[%0], [%1], %2, [%3];" \
                 :: "r"(dst), "l"(src), "r"(bytes), "r"(mbar) : "memory")

#define LDSM_X4(r0, r1, r2, r3, a) \
    asm volatile("ldmatrix.sync.aligned.m8n8.x4.shared.b16 {%0,%1,%2,%3}, [%4];" \
        : "=r"(r0), "=r"(r1), "=r"(r2), "=r"(r3) : "r"(a))

#define MMA16(d, a, b) \
    asm volatile("mma.sync.aligned.m16n8k16.row.col.f32.f16.f16.f32 " \
        "{%0,%1,%2,%3}, {%4,%5,%6,%7}, {%8,%9}, {%0,%1,%2,%3};" \
        : "+f"((d)[0]), "+f"((d)[1]), "+f"((d)[2]), "+f"((d)[3]) \
        : "r"((a)[0]), "r"((a)[1]), "r"((a)[2]), "r"((a)[3]), \
          "r"((b)[0]), "r"((b)[1]))

__device__ __forceinline__ ll toff(int row, int k, int kc) {
    int r = row & 127;
    int quad = ((k >> 3) & 3) ^ ((r >> 1) & 3);
    return ((ll)((row >> 7) * kc + (k >> 5)) * 128 + r) * 32 + quad * 8 + (k & 7);
}

__device__ __forceinline__ void splitw_t(__half* hp, __half* lp, int row, int k,
                                         int kc, float v) {
    ll i = toff(row, k, kc);
    __half h = __float2half_rn(v);
    hp[i] = h;
    lp[i] = __float2half_rn(v - __half2float(h));
}
__device__ __forceinline__ void splitw2_t(__half* hp, __half* lp, int row, int k,
                                          int kc, float v0, float v1) {
    ll i = toff(row, k, kc);
    __half h0 = __float2half_rn(v0), h1 = __float2half_rn(v1);
    *(__half2*)(hp + i) = __halves2half2(h0, h1);
    *(__half2*)(lp + i) = __halves2half2(
        __float2half_rn(v0 - __half2float(h0)),
        __float2half_rn(v1 - __half2float(h1)));
}
__device__ __forceinline__ void hi2_t(__half* hp, int row, int k, int kc,
                                      float v0, float v1) {
    ll i = toff(row, k, kc);
    *(__half2*)(hp + i) = __halves2half2(__float2half_rn(v0), __float2half_rn(v1));
}
__device__ __forceinline__ void splitw8_t(__half* hp, __half* lp, int row, int k,
                                          int kc, const float* f) {
    ll i = toff(row, k, kc);
    uint32_t hw[4], lw[4];
#pragma unroll
    for (int j = 0; j < 4; j++) {
        __half a = __float2half_rn(f[2*j]), b = __float2half_rn(f[2*j+1]);
        __half2 hh = __halves2half2(a, b);
        hw[j] = *(uint32_t*)&hh;
        __half2 l2 = __halves2half2(
            __float2half_rn(f[2*j]   - __half2float(a)),
            __float2half_rn(f[2*j+1] - __half2float(b)));
        lw[j] = *(uint32_t*)&l2;
    }
    *(uint4*)(hp + i) = make_uint4(hw[0], hw[1], hw[2], hw[3]);
    *(uint4*)(lp + i) = make_uint4(lw[0], lw[1], lw[2], lw[3]);
}
__device__ __forceinline__ void hi8_t(__half* hp, int row, int k, int kc,
                                      const float* f) {
    ll i = toff(row, k, kc);
    uint32_t hw[4];
#pragma unroll
    for (int j = 0; j < 4; j++) {
        __half2 hh = __halves2half2(__float2half_rn(f[2*j]),
                                    __float2half_rn(f[2*j+1]));
        hw[j] = *(uint32_t*)&hh;
    }
    *(uint4*)(hp + i) = make_uint4(hw[0], hw[1], hw[2], hw[3]);
}

struct Op { const __half* h; const __half* l; int kc; };

// ===== heavy GEMM: 128x128 tile, 256 threads, hi-only, 2 CTAs/SM ==========
// stage: Ah@0, Bh@8K ; stride 16384 ; 4-stage ring (64KB) + mbars + rowsum
#define HST 16384u
#define SMH 66112

// MODE 1: spk = (acc+bias[n])*aux[b,n] -> hi-plane only
// MODE 2: logit[m] += sum_n relu(acc+aux[b,n])*uv[b,n]
template<int MODE>
__global__ __launch_bounds__(256, 2)
void tc_gemm(Op A1, Op A2, Op B1, Op B2, int K,
             __half* __restrict__ Ch,
             int okc, const float* __restrict__ bias,
             const float* __restrict__ aux, const float* __restrict__ uv,
             float* __restrict__ logit)
{
    extern __shared__ char smem[];
    const uint32_t su = smem_u32(smem);
    const int tid = threadIdx.x;
    const int lane = tid & 31, wid = tid >> 5;
    const int wm = wid & 3, wn = wid >> 2;     // 4m x 2n warps
    const int m0 = blockIdx.y * 128, n0 = blockIdx.x * 128;
    const int NC = K >> 5;
    const uint32_t mbF = su + 65536u, mbE = su + 65568u;

    if (tid == 0) {
#pragma unroll
        for (int s = 0; s < 4; s++) {
            MBARRIER_INIT(mbF + s * 8, 1);
            MBARRIER_INIT(mbE + s * 8, 8);
        }
        FENCE_ASYNC();
    }
    __syncthreads();

    auto issue = [&](int cn) {
        const bool a1 = cn < A1.kc, b1 = cn < B1.kc;
        const __half* ah = a1 ? A1.h : A2.h;
        const __half* bh = b1 ? B1.h : B2.h;
        const int ca = a1 ? cn : cn - A1.kc;
        const int cb = b1 ? cn : cn - B1.kc;
        const int kca = a1 ? A1.kc : A2.kc;
        const int kcb = b1 ? B1.kc : B2.kc;
        const ll ao = ((ll)((m0 >> 7) * kca + ca)) * 8192;
        const ll bo = ((ll)((n0 >> 7) * kcb + cb)) * 8192;
        const uint32_t st = su + (uint32_t)(cn & 3) * HST;
        const uint32_t mb = mbF + (cn & 3) * 8;
        MBARRIER_EXPECT_TX(mb, 16384u);
        BULK_G2S(st,          (const char*)ah + ao, 8192u, mb);
        BULK_G2S(st + 8192u,  (const char*)bh + bo, 8192u, mb);
    };

    if (tid == 0) {
        issue(0);
        if (NC > 1) issue(1);
        if (NC > 2) issue(2);
    }

    int ba[2], sa2[2], bb[4], sb2[4];
#pragma unroll
    for (int tm = 0; tm < 2; tm++) {
        int r = wm * 32 + tm * 16 + (lane & 7) + ((lane >> 3) & 1) * 8;
        ba[tm] = r * 64; sa2[tm] = (r >> 1) & 3;
    }
#pragma unroll
    for (int tp = 0; tp < 4; tp++) {
        int r = wn * 64 + tp * 16 + (lane & 7) + (lane >> 4) * 8;
        bb[tp] = r * 64; sb2[tp] = (r >> 1) & 3;
    }
    const int qa = lane >> 4, qb = (lane >> 3) & 1;

    float acc[2][8][4];
#pragma unroll
    for (int i = 0; i < 2; i++)
#pragma unroll
        for (int j = 0; j < 8; j++)
#pragma unroll
            for (int r = 0; r < 4; r++) acc[i][j][r] = 0.f;

    for (int c = 0; c < NC; c++) {
        // rotating producer warp
        if (wid == (c & 7) && lane == 0 && c + 3 < NC) {
            const int cn = c + 3;
            if (cn >= 4)
                MBARRIER_WAIT_PARITY(mbE + (cn & 3) * 8, ((cn >> 2) - 1) & 1);
            issue(cn);
        }
        MBARRIER_WAIT_PARITY(mbF + (c & 3) * 8, (c >> 2) & 1);
        const uint32_t st = su + (uint32_t)(c & 3) * HST;
#pragma unroll
        for (int kk2 = 0; kk2 < 2; kk2++) {
            uint32_t ah[2][4], bh[8][2];
#pragma unroll
            for (int tm = 0; tm < 2; tm++) {
                const uint32_t ad = st + ba[tm]
                    + (uint32_t)((((qa + kk2 * 2) ^ sa2[tm]) & 3) * 16);
                LDSM_X4(ah[tm][0], ah[tm][1], ah[tm][2], ah[tm][3], ad);
            }
#pragma unroll
            for (int tp = 0; tp < 4; tp++) {
                const uint32_t bd = st + 8192u + bb[tp]
                    + (uint32_t)((((qb + kk2 * 2) ^ sb2[tp]) & 3) * 16);
                uint32_t r0, r1, r2, r3;
                LDSM_X4(r0, r1, r2, r3, bd);
                bh[2*tp][0] = r0; bh[2*tp][1] = r1;
                bh[2*tp+1][0] = r2; bh[2*tp+1][1] = r3;
            }
#pragma unroll
            for (int tm = 0; tm < 2; tm++)
#pragma unroll
                for (int tn = 0; tn < 8; tn++)
                    MMA16(acc[tm][tn], ah[tm], bh[tn]);
        }
        if (lane == 0) MBARRIER_ARRIVE(mbE + (c & 3) * 8);
    }

    float* rowsum = (float*)(smem + 65600);
    if (MODE == 2) {
        __syncthreads();
        if (tid < 128) rowsum[tid] = 0.f;
        __syncthreads();
    }

#pragma unroll
    for (int tm = 0; tm < 2; tm++) {
        const int lr0 = wm * 32 + tm * 16 + (lane >> 2);
        const int r0 = m0 + lr0, r1 = r0 + 8;
        const int b0 = r0 / NHW, b1 = r1 / NHW;
        if (MODE == 1) {
#pragma unroll
            for (int tn = 0; tn < 8; tn++) {
                const int gn = n0 + wn * 64 + tn * 8 + (lane & 3) * 2;
                const float bb0 = bias[gn], bb1 = bias[gn + 1];
                const float* a0 = aux + (ll)b0 * 512 + gn;
                const float* a1 = aux + (ll)b1 * 512 + gn;
                hi2_t(Ch, r0, gn, okc,
                      (acc[tm][tn][0] + bb0) * a0[0],
                      (acc[tm][tn][1] + bb1) * a0[1]);
                hi2_t(Ch, r1, gn, okc,
                      (acc[tm][tn][2] + bb0) * a1[0],
                      (acc[tm][tn][3] + bb1) * a1[1]);
            }
        } else {
            float p0 = 0.f, p1 = 0.f;
#pragma unroll
            for (int tn = 0; tn < 8; tn++) {
                const int gn = n0 + wn * 64 + tn * 8 + (lane & 3) * 2;
                const float* x0 = aux + (ll)b0 * 512 + gn;
                const float* u0 = uv  + (ll)b0 * 512 + gn;
                const float* x1 = aux + (ll)b1 * 512 + gn;
                const float* u1 = uv  + (ll)b1 * 512 + gn;
                p0 += fmaxf(acc[tm][tn][0] + x0[0], 0.f) * u0[0]
                    + fmaxf(acc[tm][tn][1] + x0[1], 0.f) * u0[1];
                p1 += fmaxf(acc[tm][tn][2] + x1[0], 0.f) * u1[0]
                    + fmaxf(acc[tm][tn][3] + x1[1], 0.f) * u1[1];
            }
            p0 += __shfl_xor_sync(0xffffffffu, p0, 1);
            p0 += __shfl_xor_sync(0xffffffffu, p0, 2);
            p1 += __shfl_xor_sync(0xffffffffu, p1, 1);
            p1 += __shfl_xor_sync(0xffffffffu, p1, 2);
            if ((lane & 3) == 0) {
                atomicAdd(&rowsum[lr0], p0);
                atomicAdd(&rowsum[lr0 + 8], p1);
            }
        }
    }
    if (MODE == 2) {
        __syncthreads();
        if (tid < 128) atomicAdd(&logit[m0 + tid], rowsum[tid]);
    }
}

// ============ batched small GEMM (full precision, unchanged) ===============
struct GD {
    const __half *ah, *al; int akc;
    const __half *bh, *bl; int bkc;
    int K;
    float* C; __half* Ch; __half* Cl; int okc;
    const float* bias; int act; int atomic; int my;
};
struct GDBatch { GD d[4]; };

#define SMB 131712

__global__ __launch_bounds__(512, 1)
void tc_gemmb(GDBatch tb)
{
    const GD g = tb.d[blockIdx.z];
    if (blockIdx.y >= g.my) return;
    extern __shared__ char smem[];
    const uint32_t su = smem_u32(smem);
    const int tid = threadIdx.x;
    const int lane = tid & 31, wid = tid >> 5;
    const int wm = wid & 3, wn = wid >> 2;
    const int m0 = blockIdx.y * 128, n0 = blockIdx.x * 128;
    const int NC = g.K >> 5;
    const uint32_t mbF = su + 131072u, mbE = su + 131104u;

    if (tid == 0) {
#pragma unroll
        for (int s = 0; s < 4; s++) {
            MBARRIER_INIT(mbF + s * 8, 1);
            MBARRIER_INIT(mbE + s * 8, 16);
        }
        FENCE_ASYNC();
    }
    __syncthreads();

    auto issue = [&](int cn) {
        const ll ao = ((ll)((m0 >> 7) * g.akc + cn)) * 8192;
        const ll bo = ((ll)((n0 >> 7) * g.bkc + cn)) * 8192;
        const uint32_t st = su + (uint32_t)(cn & 3) * 32768u;
        const uint32_t mb = mbF + (cn & 3) * 8;
        MBARRIER_EXPECT_TX(mb, 32768u);
        BULK_G2S(st,           (const char*)g.ah + ao, 8192u, mb);
        BULK_G2S(st + 8192u,   (const char*)g.al + ao, 8192u, mb);
        BULK_G2S(st + 16384u,  (const char*)g.bh + bo, 8192u, mb);
        BULK_G2S(st + 24576u,  (const char*)g.bl + bo, 8192u, mb);
    };

    if (tid == 0) { issue(0); if (NC > 1) issue(1); if (NC > 2) issue(2); }

    int ba[2], sa2[2], bb[2], sb2[2];
#pragma unroll
    for (int tm = 0; tm < 2; tm++) {
        int r = wm * 32 + tm * 16 + (lane & 7) + ((lane >> 3) & 1) * 8;
        ba[tm] = r * 64; sa2[tm] = (r >> 1) & 3;
    }
#pragma unroll
    for (int tp = 0; tp < 2; tp++) {
        int r = wn * 32 + tp * 16 + (lane & 7) + (lane >> 4) * 8;
        bb[tp] = r * 64; sb2[tp] = (r >> 1) & 3;
    }
    const int qa = lane >> 4, qb = (lane >> 3) & 1;

    float acc[2][4][4];
#pragma unroll
    for (int i = 0; i < 2; i++)
#pragma unroll
        for (int j = 0; j < 4; j++)
#pragma unroll
            for (int r = 0; r < 4; r++) acc[i][j][r] = 0.f;

    for (int c = 0; c < NC; c++) {
        if (tid == 0 && c + 3 < NC) {
            const int cn = c + 3;
            if (cn >= 4)
                MBARRIER_WAIT_PARITY(mbE + (cn & 3) * 8, ((cn >> 2) - 1) & 1);
            issue(cn);
        }
        MBARRIER_WAIT_PARITY(mbF + (c & 3) * 8, (c >> 2) & 1);
        const uint32_t st = su + (uint32_t)(c & 3) * 32768u;
#pragma unroll
        for (int kk2 = 0; kk2 < 2; kk2++) {
            uint32_t ah[2][4], al[2][4], bh[4][2], bl[4][2];
#pragma unroll
            for (int tm = 0; tm < 2; tm++) {
                const uint32_t ad = st + ba[tm]
                    + (uint32_t)((((qa + kk2 * 2) ^ sa2[tm]) & 3) * 16);
                LDSM_X4(ah[tm][0], ah[tm][1], ah[tm][2], ah[tm][3], ad);
                LDSM_X4(al[tm][0], al[tm][1], al[tm][2], al[tm][3], ad + 8192u);
            }
#pragma unroll
            for (int tp = 0; tp < 2; tp++) {
                const uint32_t bd = st + 16384u + bb[tp]
                    + (uint32_t)((((qb + kk2 * 2) ^ sb2[tp]) & 3) * 16);
                uint32_t r0, r1, r2, r3;
                LDSM_X4(r0, r1, r2, r3, bd);
                bh[2*tp][0] = r0; bh[2*tp][1] = r1;
                bh[2*tp+1][0] = r2; bh[2*tp+1][1] = r3;
                LDSM_X4(r0, r1, r2, r3, bd + 8192u);
                bl[2*tp][0] = r0; bl[2*tp][1] = r1;
                bl[2*tp+1][0] = r2; bl[2*tp+1][1] = r3;
            }
#pragma unroll
            for (int tm = 0; tm < 2; tm++)
#pragma unroll
                for (int tn = 0; tn < 4; tn++) {
                    MMA16(acc[tm][tn], ah[tm], bh[tn]);
                    MMA16(acc[tm][tn], ah[tm], bl[tn]);
                    MMA16(acc[tm][tn], al[tm], bh[tn]);
                }
        }
        if (lane == 0) MBARRIER_ARRIVE(mbE + (c & 3) * 8);
    }

#pragma unroll
    for (int tm = 0; tm < 2; tm++) {
        const int lr0 = wm * 32 + tm * 16 + (lane >> 2);
        const int r0 = m0 + lr0, r1 = r0 + 8;
#pragma unroll
        for (int tn = 0; tn < 4; tn++) {
            const int gn = n0 + wn * 32 + tn * 8 + (lane & 3) * 2;
            float v0 = acc[tm][tn][0], v1 = acc[tm][tn][1];
            float v2 = acc[tm][tn][2], v3 = acc[tm][tn][3];
            if (g.bias) {
                float b0 = g.bias[gn], b1 = g.bias[gn + 1];
                v0 += b0; v1 += b1; v2 += b0; v3 += b1;
            }
            if (g.act == 1) {
                v0 = tanhf(v0); v1 = tanhf(v1);
                v2 = tanhf(v2); v3 = tanhf(v3);
            }
            if (g.atomic) {
                atomicAdd(&g.C[(ll)r0 * 512 + gn], v0);
                atomicAdd(&g.C[(ll)r0 * 512 + gn + 1], v1);
                atomicAdd(&g.C[(ll)r1 * 512 + gn], v2);
                atomicAdd(&g.C[(ll)r1 * 512 + gn + 1], v3);
            } else {
                if (g.C) {
                    *(float2*)&g.C[(ll)r0 * 512 + gn] = make_float2(v0, v1);
                    *(float2*)&g.C[(ll)r1 * 512 + gn] = make_float2(v2, v3);
                }
                if (g.Ch) {
                    splitw2_t(g.Ch, g.Cl, r0, gn, g.okc, v0, v1);
                    splitw2_t(g.Ch, g.Cl, r1, gn, g.okc, v2, v3);
                }
            }
        }
    }
}

// ===================== producers ===========================================
__global__ __launch_bounds__(256)
void transpose_k(const float* __restrict__ know, __half* __restrict__ kh)
{
    __shared__ float t[32][65];
    const int b = blockIdx.z;
    const int n0 = blockIdx.x * 32, d0 = blockIdx.y * 64;
    const int tx = threadIdx.x, ty = threadIdx.y;
#pragma unroll
    for (int r = 0; r < 8; r++) {
        int dl = ty + r * 8;
        int n = n0 + tx;
        t[tx][dl] = (n < NHW) ? know[((ll)b * ND + d0 + dl) * NHW + n] : 0.f;
    }
    __syncthreads();
    const int tid = ty * 32 + tx;
    const int nl = tid & 31, dg = tid >> 5;
    if (n0 + nl < NHW) {
        float f[8];
#pragma unroll
        for (int i = 0; i < 8; i++) f[i] = t[nl][dg * 8 + i];
        hi8_t(kh, b * NHW + n0 + nl, d0 + dg * 8, 16, f);
    }
}

struct TDesc { const float* src; __half* dh; ll E; int R; int kc; };
struct TBatch { TDesc d[9]; };

__global__ __launch_bounds__(256)
void trans_w(TBatch tb)
{
    const TDesc td = tb.d[blockIdx.z];
    const int k0 = blockIdx.y * 64, n0 = blockIdx.x * 32;
    if (k0 >= td.R) return;
    __half* dl = td.dh + td.E;
    __shared__ float t[32][65];
    const int tx = threadIdx.x, ty = threadIdx.y;
#pragma unroll
    for (int r = 0; r < 8; r++) {
        int kk = ty + r * 8;
        t[tx][kk] = td.src[(ll)(k0 + kk) * 512 + n0 + tx];
    }
    __syncthreads();
    const int tid = ty * 32 + tx;
    const int nl = tid & 31, kg = tid >> 5;
    float f[8];
#pragma unroll
    for (int i = 0; i < 8; i++) f[i] = t[nl][kg * 8 + i];
    splitw8_t(td.dh, dl, n0 + nl, k0 + kg * 8, td.kc, f);
}

__global__ void wsumT_kernel(const float* __restrict__ Wwcat,
                             __half* __restrict__ nh)
{
    int g = blockIdx.x * 256 + threadIdx.x;
    int n = g >> 6, k = (g & 63) * 8;
    float f[8];
#pragma unroll
    for (int i = 0; i < 8; i++)
        f[i] = Wwcat[(ll)(512 + k + i) * 512 + n] + Wwcat[(ll)(1024 + k + i) * 512 + n];
    splitw8_t(nh, nh + 524288, n, 512 + k, 32, f);
}

__global__ void bias2_kernel(const float* __restrict__ Wc1, const float* __restrict__ bk,
                             const float* __restrict__ bc1, float* __restrict__ b2)
{
    int d = blockIdx.x * 256 + threadIdx.x;
    int e0 = blockIdx.y * 32;
    float acc = (blockIdx.y == 0) ? bc1[d] : 0.f;
#pragma unroll
    for (int e = 0; e < 32; e++)
        acc += bk[e0 + e] * Wc1[(ll)(512 + e0 + e) * 512 + d];
    atomicAdd(&b2[d], acc);
}

__global__ void init_bufs(const float* __restrict__ bwcat,
                          char* __restrict__ Sb, float* __restrict__ outM)
{
    int i = blockIdx.x * 256 + threadIdx.x;
    ((float*)(Sb + B_QF))[i] = 0.f;
    ((float*)(Sb + B_CQ))[i] = 0.f;
    if (i < NM) ((float*)(Sb + B_LOGIT))[i] = 0.f;
    if (i < 512) ((float*)(Sb + B_BIAS2))[i] = 0.f;
    outM[i] = bwcat[i & 511];
}

__global__ void tanhsplit_kernel(const float* __restrict__ qf,
                                 const float* __restrict__ bsc,
                                 __half* __restrict__ qh)
{
    int g = blockIdx.x * 256 + threadIdx.x;
    int row = g >> 6, k = (g & 63) * 8;
    float f[8];
#pragma unroll
    for (int i = 0; i < 8; i++)
        f[i] = tanhf(qf[(ll)row * 512 + k + i] + bsc[k + i]);
    splitw8_t(qh, qh + 131072, row, k, 16, f);
}

__global__ void copy_split(const float* __restrict__ q, const float* __restrict__ c0,
                           const float* __restrict__ m0, const float* __restrict__ wc2,
                           const float* __restrict__ wk,
                           char* __restrict__ Sb)
{
    int g = blockIdx.x * 256 + threadIdx.x;
    const float* src; __half* h; ll E; int ld, kc, j;
    if (g < 32768)       { src = q;   h = (__half*)(Sb + B_QR);   E = 262144; ld = 1024; kc = 32; j = g; }
    else if (g < 49152)  { src = c0;  h = (__half*)(Sb + B_C0R);  E = 131072; ld = 512;  kc = 16; j = g - 32768; }
    else if (g < 65536)  { src = m0;  h = (__half*)(Sb + B_M0R);  E = 131072; ld = 512;  kc = 16; j = g - 49152; }
    else if (g < 98304)  { src = wc2; h = (__half*)(Sb + B_WC2R); E = 262144; ld = 512;  kc = 16; j = g - 65536; }
    else                 { src = wk;  h = (__half*)(Sb + B_WKP);  E = 262144; ld = 512;  kc = 16; j = g - 98304; }
    const int gpr = ld >> 3;
    int row = j / gpr, k = (j % gpr) * 8;
    float f[8];
    const float* s = src + (ll)row * ld + k;
#pragma unroll
    for (int i = 0; i < 8; i++) f[i] = s[i];
    splitw8_t(h, h + E, row, k, kc, f);
}

__global__ __launch_bounds__(256)
void attnc_kernel(const float* __restrict__ words, const float* __restrict__ cq,
                  const float* __restrict__ bcq,
                  const float* __restrict__ wac, const float* __restrict__ bac,
                  float* __restrict__ control)
{
    const int b = blockIdx.x, tid = threadIdx.x;
    const int warp = tid >> 5, lane = tid & 31;
    __shared__ float cw[ND];
    __shared__ float sa[NS];
    for (int d = tid; d < ND; d += 256)
        cw[d] = (cq[(ll)b * ND + d] + bcq[d]) * wac[d];
    __syncthreads();
#pragma unroll
    for (int r = 0; r < 4; r++) {
        int s = warp * 4 + r;
        const float* wp = words + ((ll)b * NS + s) * ND;
        float acc = 0.f;
        for (int d = lane; d < ND; d += 32) acc += cw[d] * wp[d];
#pragma unroll
        for (int o = 16; o; o >>= 1) acc += __shfl_xor_sync(0xffffffffu, acc, o);
        if (lane == 0) sa[s] = acc + bac[0];
    }
    __syncthreads();
    if (warp == 0) {
        float v = sa[lane], mx = v;
#pragma unroll
        for (int o = 16; o; o >>= 1) mx = fmaxf(mx, __shfl_xor_sync(0xffffffffu, mx, o));
        float e = expf(v - mx), sm = e;
#pragma unroll
        for (int o = 16; o; o >>= 1) sm += __shfl_xor_sync(0xffffffffu, sm, o);
        sa[lane] = e / sm;
    }
    __syncthreads();
    for (int d = tid; d < ND; d += 256) {
        float acc = 0.f;
#pragma unroll 8
        for (int s = 0; s < NS; s++) acc += sa[s] * words[((ll)b * NS + s) * ND + d];
        control[(ll)b * ND + d] = acc;
    }
}

__global__ void vsplit_kernel(const float* __restrict__ control,
                              const float* __restrict__ war,
                              __half* __restrict__ vh)
{
    int g = blockIdx.x * 256 + threadIdx.x;
    int b = g >> 6, k = (g & 63) * 8;
    float f[8];
#pragma unroll
    for (int i = 0; i < 8; i++)
        f[i] = control[(ll)b * 512 + k + i] * war[k + i];
    splitw8_t(vh, vh + 131072, b, k, 16, f);
}

__global__ __launch_bounds__(256)
void softmaxn_kernel(const float* __restrict__ logit, float* __restrict__ ar)
{
    const int b = blockIdx.x, tid = threadIdx.x;
    __shared__ float s[256];
    float v = (tid < NHW) ? logit[(ll)b * NHW + tid] : -1e30f;
    s[tid] = v; __syncthreads();
    for (int o = 128; o; o >>= 1) { if (tid < o) s[tid] = fmaxf(s[tid], s[tid + o]); __syncthreads(); }
    float mx = s[0]; __syncthreads();
    float e = (tid < NHW) ? expf(v - mx) : 0.f;
    s[tid] = e; __syncthreads();
    for (int o = 128; o; o >>= 1) { if (tid < o) s[tid] += s[tid + o]; __syncthreads(); }
    float sum = s[0];
    if (tid < NHW) ar[(ll)b * NHW + tid] = e / sum;
}

__global__ __launch_bounds__(256)
void read_kernel(const float* __restrict__ know, const float* __restrict__ ar,
                 __half* __restrict__ rh)
{
    const int b = blockIdx.x, tid = threadIdx.x;
    const int warp = tid >> 5, lane = tid & 31;
    __shared__ float s[NHW];
    if (tid < NHW) s[tid] = ar[(ll)b * NHW + tid];
    __syncthreads();
    for (int d = warp; d < ND; d += 8) {
        const float* kp = know + ((ll)b * ND + d) * NHW;
        float acc = 0.f;
        for (int n = lane; n < NHW; n += 32) acc += kp[n] * s[n];
#pragma unroll
        for (int o = 16; o; o >>= 1) acc += __shfl_xor_sync(0xffffffffu, acc, o);
        if (lane == 0) splitw_t(rh, rh + 131072, b, d, 16, acc);
    }
}

// ===========================================================================
extern "C" void kernel_launch(void* const* d_in, const int* in_sizes, int n_in,
                              void* d_out, int out_size)
{
    const float* words    = (const float*)d_in[0];
    const float* question = (const float*)d_in[1];
    const float* know     = (const float*)d_in[2];
    const float* control0 = (const float*)d_in[3];
    const float* memory0  = (const float*)d_in[4];
    const float* Wsc  = (const float*)d_in[5];
    const float* bsc  = (const float*)d_in[6];
    const float* Wp   = (const float*)d_in[7];
    const float* bp   = (const float*)d_in[8];
    const float* Wcq  = (const float*)d_in[9];
    const float* bcq  = (const float*)d_in[10];
    const float* wac  = (const float*)d_in[11];
    const float* bac  = (const float*)d_in[12];
    const float* Wm   = (const float*)d_in[13];
    const float* bm   = (const float*)d_in[14];
    const float* Wk   = (const float*)d_in[15];
    const float* bk   = (const float*)d_in[16];
    const float* Wc1  = (const float*)d_in[17];
    const float* bc1  = (const float*)d_in[18];
    const float* Wc2  = (const float*)d_in[19];
    const float* war  = (const float*)d_in[21];
    const float* Wwcat = (const float*)d_in[27];
    const float* bwcat = (const float*)d_in[28];

    cudaFuncSetAttribute(tc_gemm<1>, cudaFuncAttributeMaxDynamicSharedMemorySize, SMH);
    cudaFuncSetAttribute(tc_gemm<2>, cudaFuncAttributeMaxDynamicSharedMemorySize, SMH);
    cudaFuncSetAttribute(tc_gemmb, cudaFuncAttributeMaxDynamicSharedMemorySize, SMB);

    char* Sb = nullptr;
    cudaGetSymbolAddress((void**)&Sb, g_s);

    float* outC = (float*)d_out;
    float* outM = (float*)d_out + (ll)NB * ND;

    auto F  = [&](ll off) { return (float*)(Sb + off); };
    auto Hh = [&](ll off) { return (__half*)(Sb + off); };
    Op KNOWT = { Hh(B_KNOWT), nullptr, 16 };
    Op SPK   = { Hh(B_SPK),   nullptr, 16 };
    Op WKT_H = { Hh(B_WKT),   nullptr, 16 };
    Op W1A_H = { Hh(B_W1AT),  nullptr, 16 };
    Op WKW_H = { Hh(B_WKWT),  nullptr, 16 };
    Op Z = { nullptr, nullptr, 0 };

    init_bufs<<<512, 256>>>(bwcat, Sb, outM);
    {
        TBatch tb;
        tb.d[0] = { Wk,                     Hh(B_WKT),   262144, 512, 16 };
        tb.d[1] = { Wc1,                    Hh(B_W1AT),  262144, 512, 16 };
        tb.d[2] = { Wc1 + (ll)ND * ND,      Hh(B_W1BT),  262144, 512, 16 };
        tb.d[3] = { Wsc,                    Hh(B_WSCT),  524288, 1024, 32 };
        tb.d[4] = { Wp,                     Hh(B_WPT),   262144, 512, 16 };
        tb.d[5] = { Wcq,                    Hh(B_WCQT),  524288, 1024, 32 };
        tb.d[6] = { Wm,                     Hh(B_WMT),   262144, 512, 16 };
        tb.d[7] = { Wc1 + (ll)2 * ND * ND,  Hh(B_WC1CT), 262144, 512, 16 };
        tb.d[8] = { Wwcat,                  Hh(B_NMBT),  524288, 512, 32 };
        trans_w<<<dim3(16, 16, 9), dim3(32, 8)>>>(tb);
    }
    transpose_k<<<dim3(7, 8, NB), dim3(32, 8)>>>(know, Hh(B_KNOWT));
    copy_split<<<512, 256>>>(question, control0, memory0, Wc2, Wk, Sb);

    const ll CH16 = 16 * 4096;

    // batch1: q-half1, q-half2 (split-K atomic), pm, WkW1b
    {
        GDBatch b{};
        b.d[0] = { Hh(B_QR), Hh(B_QR) + 262144, 32,
                   Hh(B_WSCT), Hh(B_WSCT) + 524288, 32,
                   512, F(B_QF), nullptr, nullptr, 0, nullptr, 0, 1, 2 };
        b.d[1] = { Hh(B_QR) + CH16, Hh(B_QR) + 262144 + CH16, 32,
                   Hh(B_WSCT) + CH16, Hh(B_WSCT) + 524288 + CH16, 32,
                   512, F(B_QF), nullptr, nullptr, 0, nullptr, 0, 1, 2 };
        b.d[2] = { Hh(B_M0R), Hh(B_M0R) + 131072, 16,
                   Hh(B_WMT), Hh(B_WMT) + 262144, 16,
                   512, F(B_PMF), Hh(B_PMP), Hh(B_PMP) + 131072, 16, bm, 0, 0, 2 };
        b.d[3] = { Hh(B_W1BT), Hh(B_W1BT) + 262144, 16,
                   Hh(B_WKP), Hh(B_WKP) + 262144, 16,
                   512, nullptr, Hh(B_WKWT), Hh(B_WKWT) + 262144, 16,
                   nullptr, 0, 0, 4 };
        tc_gemmb<<<dim3(4, 4, 4), 512, SMB>>>(b);
    }

    // HEAVY 1: spk = (knowT_hi @ Wk_hi + bk) * pm[b] -> hi-plane
    tc_gemm<1><<<dim3(4, NM / 128), 256, SMH>>>(
        KNOWT, Z, WKT_H, Z, 512,
        Hh(B_SPK), 16, bk,
        F(B_PMF), nullptr, nullptr);

    wsumT_kernel<<<128, 256>>>(Wwcat, Hh(B_NMBT));
    bias2_kernel<<<dim3(2, 16), 256>>>(Wc1, bk, bc1, F(B_BIAS2));
    tanhsplit_kernel<<<64, 256>>>(F(B_QF), bsc, Hh(B_Q));

    // batch2: pa, pmc
    {
        GDBatch b{};
        b.d[0] = { Hh(B_Q), Hh(B_Q) + 131072, 16,
                   Hh(B_WPT), Hh(B_WPT) + 262144, 16,
                   512, nullptr, Hh(B_PA), Hh(B_PA) + 131072, 16, bp, 0, 0, 2 };
        b.d[1] = { Hh(B_PMP), Hh(B_PMP) + 131072, 16,
                   Hh(B_WC1CT), Hh(B_WC1CT) + 262144, 16,
                   512, F(B_PMC), nullptr, nullptr, 0, F(B_BIAS2), 0, 0, 2 };
        tc_gemmb<<<dim3(4, 2, 2), 512, SMB>>>(b);
    }
    // cq split-K batch
    {
        GDBatch b{};
        b.d[0] = { Hh(B_C0R), Hh(B_C0R) + 131072, 16,
                   Hh(B_WCQT), Hh(B_WCQT) + 524288, 32,
                   512, F(B_CQ), nullptr, nullptr, 0, nullptr, 0, 1, 2 };
        b.d[1] = { Hh(B_PA), Hh(B_PA) + 131072, 16,
                   Hh(B_WCQT) + CH16, Hh(B_WCQT) + 524288 + CH16, 32,
                   512, F(B_CQ), nullptr, nullptr, 0, nullptr, 0, 1, 2 };
        tc_gemmb<<<dim3(4, 2, 2), 512, SMB>>>(b);
    }
    attnc_kernel<<<NB, 256>>>(words, F(B_CQ), bcq, wac, bac, outC);
    vsplit_kernel<<<64, 256>>>(outC, war, Hh(B_V));
    {
        GDBatch b{};
        b.d[0] = { Hh(B_V), Hh(B_V) + 131072, 16,
                   Hh(B_WC2R), Hh(B_WC2R) + 262144, 16,
                   512, F(B_U), nullptr, nullptr, 0, nullptr, 0, 0, 2 };
        tc_gemmb<<<dim3(4, 2, 1), 512, SMB>>>(b);
    }
    // HEAVY 2: logit += relu(spk_hi@W1a_hi + knowT_hi@WkW_hi + pmc).u
    tc_gemm<2><<<dim3(4, NM / 128), 256, SMH>>>(
        SPK, KNOWT, W1A_H, WKW_H, 1024,
        nullptr, 16, nullptr,
        F(B_PMC), F(B_U), F(B_LOGIT));

    softmaxn_kernel<<<NB, 256>>>(F(B_LOGIT), F(B_AR));
    read_kernel<<<NB, 256>>>(know, F(B_AR), Hh(B_READ));

    // next_mem split-K batch
    {
        GDBatch b{};
        b.d[0] = { Hh(B_READ), Hh(B_READ) + 131072, 16,
                   Hh(B_NMBT), Hh(B_NMBT) + 524288, 32,
                   512, outM, nullptr, nullptr, 0, nullptr, 0, 1, 2 };
        b.d[1] = { Hh(B_M0R), Hh(B_M0R) + 131072, 16,
                   Hh(B_NMBT) + CH16, Hh(B_NMBT) + 524288 + CH16, 32,
                   512, outM, nullptr, nullptr, 0, nullptr, 0, 1, 2 };
        tc_gemmb<<<dim3(4, 2, 2), 512, SMB>>>(b);
    }
}

// round 15
// speedup vs baseline: 1.3478x; 1.3478x over previous
#include <cuda_runtime.h>
#include <cuda_fp16.h>
#include <cstdint>

typedef long long ll;

#define NB 256
#define NS 32
#define ND 512
#define NHW 196
#define NM (NB*NHW)   // 50176

// --------------------- scratch layout (BYTE offsets) ----------------------
#define B_Q      ((ll)0)
#define B_PA     ((ll)524288)
#define B_CQ     ((ll)1048576)
#define B_PMP    ((ll)1572864)
#define B_PMF    ((ll)2097152)
#define B_PMC    ((ll)2621440)
#define B_V      ((ll)3145728)
#define B_U      ((ll)3670016)
#define B_READ   ((ll)4194304)
#define B_BIAS2  ((ll)4719616)
#define B_LOGIT  ((ll)4721664)
#define B_AR     ((ll)4922368)
#define B_WKT    ((ll)5242880)
#define B_W1AT   ((ll)6291456)
#define B_WKWT   ((ll)7340032)
#define B_WSCT   ((ll)8388608)
#define B_WPT    ((ll)10485760)
#define B_WCQT   ((ll)11534336)
#define B_WMT    ((ll)13631488)
#define B_WC1CT  ((ll)14680064)
#define B_NMBT   ((ll)15728640)
#define B_W1BT   ((ll)17825792)
#define B_QR     ((ll)18874368)
#define B_C0R    ((ll)19922944)
#define B_M0R    ((ll)20447232)
#define B_WC2R   ((ll)20971520)
#define B_KNOWT  ((ll)22020096)    // hi-ONLY plane E=25690112
#define B_SPK    ((ll)124780544)   // hi-ONLY plane E=25690112
#define B_WKP    ((ll)227540992)
#define B_QF     ((ll)228589568)
#define B_TOTAL  ((ll)229113856)

__device__ __align__(1024) char g_s[B_TOTAL];

// ===================== arch-generic PTX helpers ============================
__device__ __forceinline__ uint32_t smem_u32(const void* p) {
    uint32_t a;
    asm("{ .reg .u64 t; cvta.to.shared.u64 t, %1; cvt.u32.u64 %0, t; }"
        : "=r"(a) : "l"(p));
    return a;
}

#define MBARRIER_INIT(addr, cnt) \
    asm volatile("mbarrier.init.shared.b64 [%0], %1;" :: "r"(addr), "r"(cnt) : "memory")
#define MBARRIER_ARRIVE(addr) \
    asm volatile("mbarrier.arrive.shared.b64 _, [%0];" :: "r"(addr) : "memory")
#define MBARRIER_EXPECT_TX(addr, bytes) \
    asm volatile("mbarrier.arrive.expect_tx.shared.b64 _, [%0], %1;" \
                 :: "r"(addr), "r"(bytes) : "memory")
#define MBARRIER_WAIT_PARITY(addr, par) do { \
    uint32_t _m = (addr), _p = (par), _d; \
    asm volatile("{ .reg .pred p; mbarrier.try_wait.parity.acquire.cta.shared::cta.b64 p, [%1], %2;" \
                 " selp.b32 %0,1,0,p; }" : "=r"(_d) : "r"(_m), "r"(_p) : "memory"); \
    if (!_d) { \
        asm volatile("{ .reg .pred P1; WL_%=:" \
                     " mbarrier.try_wait.parity.acquire.cta.shared::cta.b64 P1, [%0], %1, 0x989680;" \
                     " @P1 bra.uni WD_%=; bra.uni WL_%=; WD_%=: }" \
                     :: "r"(_m), "r"(_p) : "memory"); \
    } \
} while (0)
#define FENCE_ASYNC() asm volatile("fence.proxy.async.shared::cta;" ::: "memory")

#define BULK_G2S(dst, src, bytes, mbar) \
    asm volatile("cp.async.bulk.shared::cluster.global.mbarrier::complete_tx::bytes " \
                 "[%0], [%1], %2, [%3];" \
                 :: "r"(dst), "l"(src), "r"(bytes), "r"(mbar) : "memory")

#define LDSM_X4(r0, r1, r2, r3, a) \
    asm volatile("ldmatrix.sync.aligned.m8n8.x4.shared.b16 {%0,%1,%2,%3}, [%4];" \
        : "=r"(r0), "=r"(r1), "=r"(r2), "=r"(r3) : "r"(a))

#define MMA16(d, a, b) \
    asm volatile("mma.sync.aligned.m16n8k16.row.col.f32.f16.f16.f32 " \
        "{%0,%1,%2,%3}, {%4,%5,%6,%7}, {%8,%9}, {%0,%1,%2,%3};" \
        : "+f"((d)[0]), "+f"((d)[1]), "+f"((d)[2]), "+f"((d)[3]) \
        : "r"((a)[0]), "r"((a)[1]), "r"((a)[2]), "r"((a)[3]), \
          "r"((b)[0]), "r"((b)[1]))

__device__ __forceinline__ ll toff(int row, int k, int kc) {
    int r = row & 127;
    int quad = ((k >> 3) & 3) ^ ((r >> 1) & 3);
    return ((ll)((row >> 7) * kc + (k >> 5)) * 128 + r) * 32 + quad * 8 + (k & 7);
}

__device__ __forceinline__ void splitw_t(__half* hp, __half* lp, int row, int k,
                                         int kc, float v) {
    ll i = toff(row, k, kc);
    __half h = __float2half_rn(v);
    hp[i] = h;
    lp[i] = __float2half_rn(v - __half2float(h));
}
__device__ __forceinline__ void splitw2_t(__half* hp, __half* lp, int row, int k,
                                          int kc, float v0, float v1) {
    ll i = toff(row, k, kc);
    __half h0 = __float2half_rn(v0), h1 = __float2half_rn(v1);
    *(__half2*)(hp + i) = __halves2half2(h0, h1);
    *(__half2*)(lp + i) = __halves2half2(
        __float2half_rn(v0 - __half2float(h0)),
        __float2half_rn(v1 - __half2float(h1)));
}
__device__ __forceinline__ void hi2_t(__half* hp, int row, int k, int kc,
                                      float v0, float v1) {
    ll i = toff(row, k, kc);
    *(__half2*)(hp + i) = __halves2half2(__float2half_rn(v0), __float2half_rn(v1));
}
__device__ __forceinline__ void splitw8_t(__half* hp, __half* lp, int row, int k,
                                          int kc, const float* f) {
    ll i = toff(row, k, kc);
    uint32_t hw[4], lw[4];
#pragma unroll
    for (int j = 0; j < 4; j++) {
        __half a = __float2half_rn(f[2*j]), b = __float2half_rn(f[2*j+1]);
        __half2 hh = __halves2half2(a, b);
        hw[j] = *(uint32_t*)&hh;
        __half2 l2 = __halves2half2(
            __float2half_rn(f[2*j]   - __half2float(a)),
            __float2half_rn(f[2*j+1] - __half2float(b)));
        lw[j] = *(uint32_t*)&l2;
    }
    *(uint4*)(hp + i) = make_uint4(hw[0], hw[1], hw[2], hw[3]);
    *(uint4*)(lp + i) = make_uint4(lw[0], lw[1], lw[2], lw[3]);
}
__device__ __forceinline__ void hi8_t(__half* hp, int row, int k, int kc,
                                      const float* f) {
    ll i = toff(row, k, kc);
    uint32_t hw[4];
#pragma unroll
    for (int j = 0; j < 4; j++) {
        __half2 hh = __halves2half2(__float2half_rn(f[2*j]),
                                    __float2half_rn(f[2*j+1]));
        hw[j] = *(uint32_t*)&hh;
    }
    *(uint4*)(hp + i) = make_uint4(hw[0], hw[1], hw[2], hw[3]);
}

struct Op { const __half* h; const __half* l; int kc; };

// ===== heavy GEMM: 128m x 256n strip, hi-only, 6-stage ring (R13 + depth) ==
// stage: Ah@0, B0h@8K, B1h@16K ; stride 24576 ; 6 stages = 147456B
#define HST 24576u
#define SMH 148096

__device__ __forceinline__ void chunk_mma1(
    uint32_t st, const int* ba, const int* sa2, const int* bb, const int* sb2,
    int qa, int qb, float acc[2][2][4][4])
{
#pragma unroll
    for (int kk2 = 0; kk2 < 2; kk2++) {
        uint32_t ah[2][4];
#pragma unroll
        for (int tm = 0; tm < 2; tm++) {
            const uint32_t ad = st + ba[tm]
                + (uint32_t)((((qa + kk2 * 2) ^ sa2[tm]) & 3) * 16);
            LDSM_X4(ah[tm][0], ah[tm][1], ah[tm][2], ah[tm][3], ad);
        }
#pragma unroll
        for (int ns = 0; ns < 2; ns++) {
            uint32_t bh[4][2];
#pragma unroll
            for (int tp = 0; tp < 2; tp++) {
                const uint32_t bd = st + 8192u + (uint32_t)ns * 8192u + bb[tp]
                    + (uint32_t)((((qb + kk2 * 2) ^ sb2[tp]) & 3) * 16);
                uint32_t r0, r1, r2, r3;
                LDSM_X4(r0, r1, r2, r3, bd);
                bh[2*tp][0] = r0; bh[2*tp][1] = r1;
                bh[2*tp+1][0] = r2; bh[2*tp+1][1] = r3;
            }
#pragma unroll
            for (int tm = 0; tm < 2; tm++)
#pragma unroll
                for (int tn = 0; tn < 4; tn++)
                    MMA16(acc[ns][tm][tn], ah[tm], bh[tn]);
        }
    }
}

// MODE 1: spk = (acc+bias[n])*aux[b,n] -> hi-plane only
// MODE 2: logit[m] += sum_n relu(acc+aux[b,n])*uv[b,n]
template<int MODE>
__global__ __launch_bounds__(512, 1)
void tc_gemm(Op A1, Op A2, Op B1, Op B2, int K,
             __half* __restrict__ Ch,
             int okc, const float* __restrict__ bias,
             const float* __restrict__ aux, const float* __restrict__ uv,
             float* __restrict__ logit)
{
    extern __shared__ char smem[];
    const uint32_t su = smem_u32(smem);
    const int tid = threadIdx.x;
    const int lane = tid & 31, wid = tid >> 5;
    const int wm = wid & 3, wn = wid >> 2;
    const int m0 = blockIdx.y * 128, n0 = blockIdx.x * 256;
    const int NC = K >> 5;
    const uint32_t mbF = su + 147456u, mbE = su + 147504u;

    if (tid == 0) {
#pragma unroll
        for (int s = 0; s < 6; s++) {
            MBARRIER_INIT(mbF + s * 8, 1);
            MBARRIER_INIT(mbE + s * 8, 16);
        }
        FENCE_ASYNC();
    }
    __syncthreads();

    auto issue = [&](int cn) {
        const bool a1 = cn < A1.kc, b1 = cn < B1.kc;
        const __half* ah = a1 ? A1.h : A2.h;
        const __half* bh = b1 ? B1.h : B2.h;
        const int ca = a1 ? cn : cn - A1.kc;
        const int cb = b1 ? cn : cn - B1.kc;
        const int kca = a1 ? A1.kc : A2.kc;
        const int kcb = b1 ? B1.kc : B2.kc;
        const ll ao  = ((ll)((m0 >> 7) * kca + ca)) * 8192;
        const ll bo0 = ((ll)(((n0 >> 7) + 0) * kcb + cb)) * 8192;
        const ll bo1 = ((ll)(((n0 >> 7) + 1) * kcb + cb)) * 8192;
        const int s = cn % 6;
        const uint32_t st = su + (uint32_t)s * HST;
        const uint32_t mb = mbF + s * 8;
        MBARRIER_EXPECT_TX(mb, 24576u);
        BULK_G2S(st,           (const char*)ah + ao,  8192u, mb);
        BULK_G2S(st + 8192u,   (const char*)bh + bo0, 8192u, mb);
        BULK_G2S(st + 16384u,  (const char*)bh + bo1, 8192u, mb);
    };

    if (tid == 0) {
#pragma unroll
        for (int p = 0; p < 5; p++)
            if (p < NC) issue(p);
    }

    int ba[2], sa2[2], bb[2], sb2[2];
#pragma unroll
    for (int tm = 0; tm < 2; tm++) {
        int r = wm * 32 + tm * 16 + (lane & 7) + ((lane >> 3) & 1) * 8;
        ba[tm] = r * 64; sa2[tm] = (r >> 1) & 3;
    }
#pragma unroll
    for (int tp = 0; tp < 2; tp++) {
        int r = wn * 32 + tp * 16 + (lane & 7) + (lane >> 4) * 8;
        bb[tp] = r * 64; sb2[tp] = (r >> 1) & 3;
    }
    const int qa = lane >> 4, qb = (lane >> 3) & 1;

    float acc[2][2][4][4];
#pragma unroll
    for (int s = 0; s < 2; s++)
#pragma unroll
        for (int i = 0; i < 2; i++)
#pragma unroll
            for (int j = 0; j < 4; j++)
#pragma unroll
                for (int r = 0; r < 4; r++) acc[s][i][j][r] = 0.f;

    for (int c = 0; c < NC; c++) {
        // rotating producer warp spreads issue stalls across schedulers
        if (wid == (c & 15) && lane == 0 && c + 5 < NC) {
            const int cn = c + 5;
            if (cn >= 6)
                MBARRIER_WAIT_PARITY(mbE + (cn % 6) * 8, ((cn / 6) - 1) & 1);
            issue(cn);
        }
        MBARRIER_WAIT_PARITY(mbF + (c % 6) * 8, (c / 6) & 1);
        chunk_mma1(su + (uint32_t)(c % 6) * HST, ba, sa2, bb, sb2, qa, qb, acc);
        if (lane == 0) MBARRIER_ARRIVE(mbE + (c % 6) * 8);
    }

    float* rowsum = (float*)(smem + 147552);
    if (MODE == 2) {
        __syncthreads();
        if (tid < 128) rowsum[tid] = 0.f;
        __syncthreads();
    }

#pragma unroll
    for (int tm = 0; tm < 2; tm++) {
        const int lr0 = wm * 32 + tm * 16 + (lane >> 2);
        const int r0 = m0 + lr0, r1 = r0 + 8;
        const int b0 = r0 / NHW, b1 = r1 / NHW;
        if (MODE == 1) {
#pragma unroll
            for (int ns = 0; ns < 2; ns++)
#pragma unroll
            for (int tn = 0; tn < 4; tn++) {
                const int gn = n0 + ns * 128 + wn * 32 + tn * 8 + (lane & 3) * 2;
                const float bb0 = bias[gn], bb1 = bias[gn + 1];
                const float* a0 = aux + (ll)b0 * 512 + gn;
                const float* a1 = aux + (ll)b1 * 512 + gn;
                hi2_t(Ch, r0, gn, okc,
                      (acc[ns][tm][tn][0] + bb0) * a0[0],
                      (acc[ns][tm][tn][1] + bb1) * a0[1]);
                hi2_t(Ch, r1, gn, okc,
                      (acc[ns][tm][tn][2] + bb0) * a1[0],
                      (acc[ns][tm][tn][3] + bb1) * a1[1]);
            }
        } else {
            float p0 = 0.f, p1 = 0.f;
#pragma unroll
            for (int ns = 0; ns < 2; ns++)
#pragma unroll
            for (int tn = 0; tn < 4; tn++) {
                const int gn = n0 + ns * 128 + wn * 32 + tn * 8 + (lane & 3) * 2;
                const float* x0 = aux + (ll)b0 * 512 + gn;
                const float* u0 = uv  + (ll)b0 * 512 + gn;
                const float* x1 = aux + (ll)b1 * 512 + gn;
                const float* u1 = uv  + (ll)b1 * 512 + gn;
                p0 += fmaxf(acc[ns][tm][tn][0] + x0[0], 0.f) * u0[0]
                    + fmaxf(acc[ns][tm][tn][1] + x0[1], 0.f) * u0[1];
                p1 += fmaxf(acc[ns][tm][tn][2] + x1[0], 0.f) * u1[0]
                    + fmaxf(acc[ns][tm][tn][3] + x1[1], 0.f) * u1[1];
            }
            p0 += __shfl_xor_sync(0xffffffffu, p0, 1);
            p0 += __shfl_xor_sync(0xffffffffu, p0, 2);
            p1 += __shfl_xor_sync(0xffffffffu, p1, 1);
            p1 += __shfl_xor_sync(0xffffffffu, p1, 2);
            if ((lane & 3) == 0) {
                atomicAdd(&rowsum[lr0], p0);
                atomicAdd(&rowsum[lr0 + 8], p1);
            }
        }
    }
    if (MODE == 2) {
        __syncthreads();
        if (tid < 128) atomicAdd(&logit[m0 + tid], rowsum[tid]);
    }
}

// ============ batched small GEMM (full precision, unchanged) ===============
struct GD {
    const __half *ah, *al; int akc;
    const __half *bh, *bl; int bkc;
    int K;
    float* C; __half* Ch; __half* Cl; int okc;
    const float* bias; int act; int atomic; int my;
};
struct GDBatch { GD d[4]; };

#define SMB 131712

__global__ __launch_bounds__(512, 1)
void tc_gemmb(GDBatch tb)
{
    const GD g = tb.d[blockIdx.z];
    if (blockIdx.y >= g.my) return;
    extern __shared__ char smem[];
    const uint32_t su = smem_u32(smem);
    const int tid = threadIdx.x;
    const int lane = tid & 31, wid = tid >> 5;
    const int wm = wid & 3, wn = wid >> 2;
    const int m0 = blockIdx.y * 128, n0 = blockIdx.x * 128;
    const int NC = g.K >> 5;
    const uint32_t mbF = su + 131072u, mbE = su + 131104u;

    if (tid == 0) {
#pragma unroll
        for (int s = 0; s < 4; s++) {
            MBARRIER_INIT(mbF + s * 8, 1);
            MBARRIER_INIT(mbE + s * 8, 16);
        }
        FENCE_ASYNC();
    }
    __syncthreads();

    auto issue = [&](int cn) {
        const ll ao = ((ll)((m0 >> 7) * g.akc + cn)) * 8192;
        const ll bo = ((ll)((n0 >> 7) * g.bkc + cn)) * 8192;
        const uint32_t st = su + (uint32_t)(cn & 3) * 32768u;
        const uint32_t mb = mbF + (cn & 3) * 8;
        MBARRIER_EXPECT_TX(mb, 32768u);
        BULK_G2S(st,           (const char*)g.ah + ao, 8192u, mb);
        BULK_G2S(st + 8192u,   (const char*)g.al + ao, 8192u, mb);
        BULK_G2S(st + 16384u,  (const char*)g.bh + bo, 8192u, mb);
        BULK_G2S(st + 24576u,  (const char*)g.bl + bo, 8192u, mb);
    };

    if (tid == 0) { issue(0); if (NC > 1) issue(1); if (NC > 2) issue(2); }

    int ba[2], sa2[2], bb[2], sb2[2];
#pragma unroll
    for (int tm = 0; tm < 2; tm++) {
        int r = wm * 32 + tm * 16 + (lane & 7) + ((lane >> 3) & 1) * 8;
        ba[tm] = r * 64; sa2[tm] = (r >> 1) & 3;
    }
#pragma unroll
    for (int tp = 0; tp < 2; tp++) {
        int r = wn * 32 + tp * 16 + (lane & 7) + (lane >> 4) * 8;
        bb[tp] = r * 64; sb2[tp] = (r >> 1) & 3;
    }
    const int qa = lane >> 4, qb = (lane >> 3) & 1;

    float acc[2][4][4];
#pragma unroll
    for (int i = 0; i < 2; i++)
#pragma unroll
        for (int j = 0; j < 4; j++)
#pragma unroll
            for (int r = 0; r < 4; r++) acc[i][j][r] = 0.f;

    for (int c = 0; c < NC; c++) {
        if (tid == 0 && c + 3 < NC) {
            const int cn = c + 3;
            if (cn >= 4)
                MBARRIER_WAIT_PARITY(mbE + (cn & 3) * 8, ((cn >> 2) - 1) & 1);
            issue(cn);
        }
        MBARRIER_WAIT_PARITY(mbF + (c & 3) * 8, (c >> 2) & 1);
        const uint32_t st = su + (uint32_t)(c & 3) * 32768u;
#pragma unroll
        for (int kk2 = 0; kk2 < 2; kk2++) {
            uint32_t ah[2][4], al[2][4], bh[4][2], bl[4][2];
#pragma unroll
            for (int tm = 0; tm < 2; tm++) {
                const uint32_t ad = st + ba[tm]
                    + (uint32_t)((((qa + kk2 * 2) ^ sa2[tm]) & 3) * 16);
                LDSM_X4(ah[tm][0], ah[tm][1], ah[tm][2], ah[tm][3], ad);
                LDSM_X4(al[tm][0], al[tm][1], al[tm][2], al[tm][3], ad + 8192u);
            }
#pragma unroll
            for (int tp = 0; tp < 2; tp++) {
                const uint32_t bd = st + 16384u + bb[tp]
                    + (uint32_t)((((qb + kk2 * 2) ^ sb2[tp]) & 3) * 16);
                uint32_t r0, r1, r2, r3;
                LDSM_X4(r0, r1, r2, r3, bd);
                bh[2*tp][0] = r0; bh[2*tp][1] = r1;
                bh[2*tp+1][0] = r2; bh[2*tp+1][1] = r3;
                LDSM_X4(r0, r1, r2, r3, bd + 8192u);
                bl[2*tp][0] = r0; bl[2*tp][1] = r1;
                bl[2*tp+1][0] = r2; bl[2*tp+1][1] = r3;
            }
#pragma unroll
            for (int tm = 0; tm < 2; tm++)
#pragma unroll
                for (int tn = 0; tn < 4; tn++) {
                    MMA16(acc[tm][tn], ah[tm], bh[tn]);
                    MMA16(acc[tm][tn], ah[tm], bl[tn]);
                    MMA16(acc[tm][tn], al[tm], bh[tn]);
                }
        }
        if (lane == 0) MBARRIER_ARRIVE(mbE + (c & 3) * 8);
    }

#pragma unroll
    for (int tm = 0; tm < 2; tm++) {
        const int lr0 = wm * 32 + tm * 16 + (lane >> 2);
        const int r0 = m0 + lr0, r1 = r0 + 8;
#pragma unroll
        for (int tn = 0; tn < 4; tn++) {
            const int gn = n0 + wn * 32 + tn * 8 + (lane & 3) * 2;
            float v0 = acc[tm][tn][0], v1 = acc[tm][tn][1];
            float v2 = acc[tm][tn][2], v3 = acc[tm][tn][3];
            if (g.bias) {
                float b0 = g.bias[gn], b1 = g.bias[gn + 1];
                v0 += b0; v1 += b1; v2 += b0; v3 += b1;
            }
            if (g.act == 1) {
                v0 = tanhf(v0); v1 = tanhf(v1);
                v2 = tanhf(v2); v3 = tanhf(v3);
            }
            if (g.atomic) {
                atomicAdd(&g.C[(ll)r0 * 512 + gn], v0);
                atomicAdd(&g.C[(ll)r0 * 512 + gn + 1], v1);
                atomicAdd(&g.C[(ll)r1 * 512 + gn], v2);
                atomicAdd(&g.C[(ll)r1 * 512 + gn + 1], v3);
            } else {
                if (g.C) {
                    *(float2*)&g.C[(ll)r0 * 512 + gn] = make_float2(v0, v1);
                    *(float2*)&g.C[(ll)r1 * 512 + gn] = make_float2(v2, v3);
                }
                if (g.Ch) {
                    splitw2_t(g.Ch, g.Cl, r0, gn, g.okc, v0, v1);
                    splitw2_t(g.Ch, g.Cl, r1, gn, g.okc, v2, v3);
                }
            }
        }
    }
}

// ===================== producers ===========================================
__global__ __launch_bounds__(256)
void transpose_k(const float* __restrict__ know, __half* __restrict__ kh)
{
    __shared__ float t[32][65];
    const int b = blockIdx.z;
    const int n0 = blockIdx.x * 32, d0 = blockIdx.y * 64;
    const int tx = threadIdx.x, ty = threadIdx.y;
#pragma unroll
    for (int r = 0; r < 8; r++) {
        int dl = ty + r * 8;
        int n = n0 + tx;
        t[tx][dl] = (n < NHW) ? know[((ll)b * ND + d0 + dl) * NHW + n] : 0.f;
    }
    __syncthreads();
    const int tid = ty * 32 + tx;
    const int nl = tid & 31, dg = tid >> 5;
    if (n0 + nl < NHW) {
        float f[8];
#pragma unroll
        for (int i = 0; i < 8; i++) f[i] = t[nl][dg * 8 + i];
        hi8_t(kh, b * NHW + n0 + nl, d0 + dg * 8, 16, f);
    }
}

struct TDesc { const float* src; __half* dh; ll E; int R; int kc; };
struct TBatch { TDesc d[9]; };

__global__ __launch_bounds__(256)
void trans_w(TBatch tb)
{
    const TDesc td = tb.d[blockIdx.z];
    const int k0 = blockIdx.y * 64, n0 = blockIdx.x * 32;
    if (k0 >= td.R) return;
    __half* dl = td.dh + td.E;
    __shared__ float t[32][65];
    const int tx = threadIdx.x, ty = threadIdx.y;
#pragma unroll
    for (int r = 0; r < 8; r++) {
        int kk = ty + r * 8;
        t[tx][kk] = td.src[(ll)(k0 + kk) * 512 + n0 + tx];
    }
    __syncthreads();
    const int tid = ty * 32 + tx;
    const int nl = tid & 31, kg = tid >> 5;
    float f[8];
#pragma unroll
    for (int i = 0; i < 8; i++) f[i] = t[nl][kg * 8 + i];
    splitw8_t(td.dh, dl, n0 + nl, k0 + kg * 8, td.kc, f);
}

__global__ void wsumT_kernel(const float* __restrict__ Wwcat,
                             __half* __restrict__ nh)
{
    int g = blockIdx.x * 256 + threadIdx.x;
    int n = g >> 6, k = (g & 63) * 8;
    float f[8];
#pragma unroll
    for (int i = 0; i < 8; i++)
        f[i] = Wwcat[(ll)(512 + k + i) * 512 + n] + Wwcat[(ll)(1024 + k + i) * 512 + n];
    splitw8_t(nh, nh + 524288, n, 512 + k, 32, f);
}

__global__ void bias2_kernel(const float* __restrict__ Wc1, const float* __restrict__ bk,
                             const float* __restrict__ bc1, float* __restrict__ b2)
{
    int d = blockIdx.x * 256 + threadIdx.x;
    int e0 = blockIdx.y * 32;
    float acc = (blockIdx.y == 0) ? bc1[d] : 0.f;
#pragma unroll
    for (int e = 0; e < 32; e++)
        acc += bk[e0 + e] * Wc1[(ll)(512 + e0 + e) * 512 + d];
    atomicAdd(&b2[d], acc);
}

__global__ void init_bufs(const float* __restrict__ bwcat,
                          char* __restrict__ Sb, float* __restrict__ outM)
{
    int i = blockIdx.x * 256 + threadIdx.x;
    ((float*)(Sb + B_QF))[i] = 0.f;
    ((float*)(Sb + B_CQ))[i] = 0.f;
    if (i < NM) ((float*)(Sb + B_LOGIT))[i] = 0.f;
    if (i < 512) ((float*)(Sb + B_BIAS2))[i] = 0.f;
    outM[i] = bwcat[i & 511];
}

__global__ void tanhsplit_kernel(const float* __restrict__ qf,
                                 const float* __restrict__ bsc,
                                 __half* __restrict__ qh)
{
    int g = blockIdx.x * 256 + threadIdx.x;
    int row = g >> 6, k = (g & 63) * 8;
    float f[8];
#pragma unroll
    for (int i = 0; i < 8; i++)
        f[i] = tanhf(qf[(ll)row * 512 + k + i] + bsc[k + i]);
    splitw8_t(qh, qh + 131072, row, k, 16, f);
}

__global__ void copy_split(const float* __restrict__ q, const float* __restrict__ c0,
                           const float* __restrict__ m0, const float* __restrict__ wc2,
                           const float* __restrict__ wk,
                           char* __restrict__ Sb)
{
    int g = blockIdx.x * 256 + threadIdx.x;
    const float* src; __half* h; ll E; int ld, kc, j;
    if (g < 32768)       { src = q;   h = (__half*)(Sb + B_QR);   E = 262144; ld = 1024; kc = 32; j = g; }
    else if (g < 49152)  { src = c0;  h = (__half*)(Sb + B_C0R);  E = 131072; ld = 512;  kc = 16; j = g - 32768; }
    else if (g < 65536)  { src = m0;  h = (__half*)(Sb + B_M0R);  E = 131072; ld = 512;  kc = 16; j = g - 49152; }
    else if (g < 98304)  { src = wc2; h = (__half*)(Sb + B_WC2R); E = 262144; ld = 512;  kc = 16; j = g - 65536; }
    else                 { src = wk;  h = (__half*)(Sb + B_WKP);  E = 262144; ld = 512;  kc = 16; j = g - 98304; }
    const int gpr = ld >> 3;
    int row = j / gpr, k = (j % gpr) * 8;
    float f[8];
    const float* s = src + (ll)row * ld + k;
#pragma unroll
    for (int i = 0; i < 8; i++) f[i] = s[i];
    splitw8_t(h, h + E, row, k, kc, f);
}

__global__ __launch_bounds__(256)
void attnc_kernel(const float* __restrict__ words, const float* __restrict__ cq,
                  const float* __restrict__ bcq,
                  const float* __restrict__ wac, const float* __restrict__ bac,
                  float* __restrict__ control)
{
    const int b = blockIdx.x, tid = threadIdx.x;
    const int warp = tid >> 5, lane = tid & 31;
    __shared__ float cw[ND];
    __shared__ float sa[NS];
    for (int d = tid; d < ND; d += 256)
        cw[d] = (cq[(ll)b * ND + d] + bcq[d]) * wac[d];
    __syncthreads();
#pragma unroll
    for (int r = 0; r < 4; r++) {
        int s = warp * 4 + r;
        const float* wp = words + ((ll)b * NS + s) * ND;
        float acc = 0.f;
        for (int d = lane; d < ND; d += 32) acc += cw[d] * wp[d];
#pragma unroll
        for (int o = 16; o; o >>= 1) acc += __shfl_xor_sync(0xffffffffu, acc, o);
        if (lane == 0) sa[s] = acc + bac[0];
    }
    __syncthreads();
    if (warp == 0) {
        float v = sa[lane], mx = v;
#pragma unroll
        for (int o = 16; o; o >>= 1) mx = fmaxf(mx, __shfl_xor_sync(0xffffffffu, mx, o));
        float e = expf(v - mx), sm = e;
#pragma unroll
        for (int o = 16; o; o >>= 1) sm += __shfl_xor_sync(0xffffffffu, sm, o);
        sa[lane] = e / sm;
    }
    __syncthreads();
    for (int d = tid; d < ND; d += 256) {
        float acc = 0.f;
#pragma unroll 8
        for (int s = 0; s < NS; s++) acc += sa[s] * words[((ll)b * NS + s) * ND + d];
        control[(ll)b * ND + d] = acc;
    }
}

__global__ void vsplit_kernel(const float* __restrict__ control,
                              const float* __restrict__ war,
                              __half* __restrict__ vh)
{
    int g = blockIdx.x * 256 + threadIdx.x;
    int b = g >> 6, k = (g & 63) * 8;
    float f[8];
#pragma unroll
    for (int i = 0; i < 8; i++)
        f[i] = control[(ll)b * 512 + k + i] * war[k + i];
    splitw8_t(vh, vh + 131072, b, k, 16, f);
}

__global__ __launch_bounds__(256)
void softmaxn_kernel(const float* __restrict__ logit, float* __restrict__ ar)
{
    const int b = blockIdx.x, tid = threadIdx.x;
    __shared__ float s[256];
    float v = (tid < NHW) ? logit[(ll)b * NHW + tid] : -1e30f;
    s[tid] = v; __syncthreads();
    for (int o = 128; o; o >>= 1) { if (tid < o) s[tid] = fmaxf(s[tid], s[tid + o]); __syncthreads(); }
    float mx = s[0]; __syncthreads();
    float e = (tid < NHW) ? expf(v - mx) : 0.f;
    s[tid] = e; __syncthreads();
    for (int o = 128; o; o >>= 1) { if (tid < o) s[tid] += s[tid + o]; __syncthreads(); }
    float sum = s[0];
    if (tid < NHW) ar[(ll)b * NHW + tid] = e / sum;
}

__global__ __launch_bounds__(256)
void read_kernel(const float* __restrict__ know, const float* __restrict__ ar,
                 __half* __restrict__ rh)
{
    const int b = blockIdx.x, tid = threadIdx.x;
    const int warp = tid >> 5, lane = tid & 31;
    __shared__ float s[NHW];
    if (tid < NHW) s[tid] = ar[(ll)b * NHW + tid];
    __syncthreads();
    for (int d = warp; d < ND; d += 8) {
        const float* kp = know + ((ll)b * ND + d) * NHW;
        float acc = 0.f;
        for (int n = lane; n < NHW; n += 32) acc += kp[n] * s[n];
#pragma unroll
        for (int o = 16; o; o >>= 1) acc += __shfl_xor_sync(0xffffffffu, acc, o);
        if (lane == 0) splitw_t(rh, rh + 131072, b, d, 16, acc);
    }
}

// ===========================================================================
extern "C" void kernel_launch(void* const* d_in, const int* in_sizes, int n_in,
                              void* d_out, int out_size)
{
    const float* words    = (const float*)d_in[0];
    const float* question = (const float*)d_in[1];
    const float* know     = (const float*)d_in[2];
    const float* control0 = (const float*)d_in[3];
    const float* memory0  = (const float*)d_in[4];
    const float* Wsc  = (const float*)d_in[5];
    const float* bsc  = (const float*)d_in[6];
    const float* Wp   = (const float*)d_in[7];
    const float* bp   = (const float*)d_in[8];
    const float* Wcq  = (const float*)d_in[9];
    const float* bcq  = (const float*)d_in[10];
    const float* wac  = (const float*)d_in[11];
    const float* bac  = (const float*)d_in[12];
    const float* Wm   = (const float*)d_in[13];
    const float* bm   = (const float*)d_in[14];
    const float* Wk   = (const float*)d_in[15];
    const float* bk   = (const float*)d_in[16];
    const float* Wc1  = (const float*)d_in[17];
    const float* bc1  = (const float*)d_in[18];
    const float* Wc2  = (const float*)d_in[19];
    const float* war  = (const float*)d_in[21];
    const float* Wwcat = (const float*)d_in[27];
    const float* bwcat = (const float*)d_in[28];

    cudaFuncSetAttribute(tc_gemm<1>, cudaFuncAttributeMaxDynamicSharedMemorySize, SMH);
    cudaFuncSetAttribute(tc_gemm<2>, cudaFuncAttributeMaxDynamicSharedMemorySize, SMH);
    cudaFuncSetAttribute(tc_gemmb, cudaFuncAttributeMaxDynamicSharedMemorySize, SMB);

    char* Sb = nullptr;
    cudaGetSymbolAddress((void**)&Sb, g_s);

    float* outC = (float*)d_out;
    float* outM = (float*)d_out + (ll)NB * ND;

    auto F  = [&](ll off) { return (float*)(Sb + off); };
    auto Hh = [&](ll off) { return (__half*)(Sb + off); };
    Op KNOWT = { Hh(B_KNOWT), nullptr, 16 };
    Op SPK   = { Hh(B_SPK),   nullptr, 16 };
    Op WKT_H = { Hh(B_WKT),   nullptr, 16 };
    Op W1A_H = { Hh(B_W1AT),  nullptr, 16 };
    Op WKW_H = { Hh(B_WKWT),  nullptr, 16 };
    Op Z = { nullptr, nullptr, 0 };

    init_bufs<<<512, 256>>>(bwcat, Sb, outM);
    {
        TBatch tb;
        tb.d[0] = { Wk,                     Hh(B_WKT),   262144, 512, 16 };
        tb.d[1] = { Wc1,                    Hh(B_W1AT),  262144, 512, 16 };
        tb.d[2] = { Wc1 + (ll)ND * ND,      Hh(B_W1BT),  262144, 512, 16 };
        tb.d[3] = { Wsc,                    Hh(B_WSCT),  524288, 1024, 32 };
        tb.d[4] = { Wp,                     Hh(B_WPT),   262144, 512, 16 };
        tb.d[5] = { Wcq,                    Hh(B_WCQT),  524288, 1024, 32 };
        tb.d[6] = { Wm,                     Hh(B_WMT),   262144, 512, 16 };
        tb.d[7] = { Wc1 + (ll)2 * ND * ND,  Hh(B_WC1CT), 262144, 512, 16 };
        tb.d[8] = { Wwcat,                  Hh(B_NMBT),  524288, 512, 32 };
        trans_w<<<dim3(16, 16, 9), dim3(32, 8)>>>(tb);
    }
    transpose_k<<<dim3(7, 8, NB), dim3(32, 8)>>>(know, Hh(B_KNOWT));
    copy_split<<<512, 256>>>(question, control0, memory0, Wc2, Wk, Sb);

    const ll CH16 = 16 * 4096;

    // batch1: q-half1, q-half2 (split-K atomic), pm, WkW1b
    {
        GDBatch b{};
        b.d[0] = { Hh(B_QR), Hh(B_QR) + 262144, 32,
                   Hh(B_WSCT), Hh(B_WSCT) + 524288, 32,
                   512, F(B_QF), nullptr, nullptr, 0, nullptr, 0, 1, 2 };
        b.d[1] = { Hh(B_QR) + CH16, Hh(B_QR) + 262144 + CH16, 32,
                   Hh(B_WSCT) + CH16, Hh(B_WSCT) + 524288 + CH16, 32,
                   512, F(B_QF), nullptr, nullptr, 0, nullptr, 0, 1, 2 };
        b.d[2] = { Hh(B_M0R), Hh(B_M0R) + 131072, 16,
                   Hh(B_WMT), Hh(B_WMT) + 262144, 16,
                   512, F(B_PMF), Hh(B_PMP), Hh(B_PMP) + 131072, 16, bm, 0, 0, 2 };
        b.d[3] = { Hh(B_W1BT), Hh(B_W1BT) + 262144, 16,
                   Hh(B_WKP), Hh(B_WKP) + 262144, 16,
                   512, nullptr, Hh(B_WKWT), Hh(B_WKWT) + 262144, 16,
                   nullptr, 0, 0, 4 };
        tc_gemmb<<<dim3(4, 4, 4), 512, SMB>>>(b);
    }

    // HEAVY 1: spk = (knowT_hi @ Wk_hi + bk) * pm[b] -> hi-plane
    tc_gemm<1><<<dim3(2, NM / 128), 512, SMH>>>(
        KNOWT, Z, WKT_H, Z, 512,
        Hh(B_SPK), 16, bk,
        F(B_PMF), nullptr, nullptr);

    wsumT_kernel<<<128, 256>>>(Wwcat, Hh(B_NMBT));
    bias2_kernel<<<dim3(2, 16), 256>>>(Wc1, bk, bc1, F(B_BIAS2));
    tanhsplit_kernel<<<64, 256>>>(F(B_QF), bsc, Hh(B_Q));

    // batch2: pa, pmc
    {
        GDBatch b{};
        b.d[0] = { Hh(B_Q), Hh(B_Q) + 131072, 16,
                   Hh(B_WPT), Hh(B_WPT) + 262144, 16,
                   512, nullptr, Hh(B_PA), Hh(B_PA) + 131072, 16, bp, 0, 0, 2 };
        b.d[1] = { Hh(B_PMP), Hh(B_PMP) + 131072, 16,
                   Hh(B_WC1CT), Hh(B_WC1CT) + 262144, 16,
                   512, F(B_PMC), nullptr, nullptr, 0, F(B_BIAS2), 0, 0, 2 };
        tc_gemmb<<<dim3(4, 2, 2), 512, SMB>>>(b);
    }
    // cq split-K batch
    {
        GDBatch b{};
        b.d[0] = { Hh(B_C0R), Hh(B_C0R) + 131072, 16,
                   Hh(B_WCQT), Hh(B_WCQT) + 524288, 32,
                   512, F(B_CQ), nullptr, nullptr, 0, nullptr, 0, 1, 2 };
        b.d[1] = { Hh(B_PA), Hh(B_PA) + 131072, 16,
                   Hh(B_WCQT) + CH16, Hh(B_WCQT) + 524288 + CH16, 32,
                   512, F(B_CQ), nullptr, nullptr, 0, nullptr, 0, 1, 2 };
        tc_gemmb<<<dim3(4, 2, 2), 512, SMB>>>(b);
    }
    attnc_kernel<<<NB, 256>>>(words, F(B_CQ), bcq, wac, bac, outC);
    vsplit_kernel<<<64, 256>>>(outC, war, Hh(B_V));
    {
        GDBatch b{};
        b.d[0] = { Hh(B_V), Hh(B_V) + 131072, 16,
                   Hh(B_WC2R), Hh(B_WC2R) + 262144, 16,
                   512, F(B_U), nullptr, nullptr, 0, nullptr, 0, 0, 2 };
        tc_gemmb<<<dim3(4, 2, 1), 512, SMB>>>(b);
    }
    // HEAVY 2: logit += relu(spk_hi@W1a_hi + knowT_hi@WkW_hi + pmc).u
    tc_gemm<2><<<dim3(2, NM / 128), 512, SMH>>>(
        SPK, KNOWT, W1A_H, WKW_H, 1024,
        nullptr, 16, nullptr,
        F(B_PMC), F(B_U), F(B_LOGIT));

    softmaxn_kernel<<<NB, 256>>>(F(B_LOGIT), F(B_AR));
    read_kernel<<<NB, 256>>>(know, F(B_AR), Hh(B_READ));

    // next_mem split-K batch
    {
        GDBatch b{};
        b.d[0] = { Hh(B_READ), Hh(B_READ) + 131072, 16,
                   Hh(B_NMBT), Hh(B_NMBT) + 524288, 32,
                   512, outM, nullptr, nullptr, 0, nullptr, 0, 1, 2 };
        b.d[1] = { Hh(B_M0R), Hh(B_M0R) + 131072, 16,
                   Hh(B_NMBT) + CH16, Hh(B_NMBT) + 524288 + CH16, 32,
                   512, outM, nullptr, nullptr, 0, nullptr, 0, 1, 2 };
        tc_gemmb<<<dim3(4, 2, 2), 512, SMB>>>(b);
    }
}

// round 16
// speedup vs baseline: 1.3598x; 1.0088x over previous
#include <cuda_runtime.h>
#include <cuda_fp16.h>
#include <cstdint>

typedef long long ll;

#define NB 256
#define NS 32
#define ND 512
#define NHW 196
#define NM (NB*NHW)   // 50176

// --------------------- scratch layout (BYTE offsets) ----------------------
#define B_Q      ((ll)0)
#define B_PA     ((ll)524288)
#define B_CQ     ((ll)1048576)
#define B_PMP    ((ll)1572864)
#define B_PMF    ((ll)2097152)
#define B_PMC    ((ll)2621440)
#define B_V      ((ll)3145728)
#define B_U      ((ll)3670016)
#define B_READ   ((ll)4194304)
#define B_BIAS2  ((ll)4719616)
#define B_LOGIT  ((ll)4721664)
#define B_AR     ((ll)4922368)
#define B_WKT    ((ll)5242880)
#define B_W1AT   ((ll)6291456)
#define B_WKWT   ((ll)7340032)
#define B_WSCT   ((ll)8388608)
#define B_WPT    ((ll)10485760)
#define B_WCQT   ((ll)11534336)
#define B_WMT    ((ll)13631488)
#define B_WC1CT  ((ll)14680064)
#define B_NMBT   ((ll)15728640)
#define B_W1BT   ((ll)17825792)
#define B_QR     ((ll)18874368)
#define B_C0R    ((ll)19922944)
#define B_M0R    ((ll)20447232)
#define B_WC2R   ((ll)20971520)
#define B_KNOWT  ((ll)22020096)    // hi-ONLY plane E=25690112
#define B_SPK    ((ll)124780544)   // hi-ONLY plane E=25690112
#define B_WKP    ((ll)227540992)
#define B_QF     ((ll)228589568)
#define B_TOTAL  ((ll)229113856)

__device__ __align__(1024) char g_s[B_TOTAL];

// ===================== arch-generic PTX helpers ============================
__device__ __forceinline__ uint32_t smem_u32(const void* p) {
    uint32_t a;
    asm("{ .reg .u64 t; cvta.to.shared.u64 t, %1; cvt.u32.u64 %0, t; }"
        : "=r"(a) : "l"(p));
    return a;
}

#define MBARRIER_INIT(addr, cnt) \
    asm volatile("mbarrier.init.shared.b64 [%0], %1;" :: "r"(addr), "r"(cnt) : "memory")
#define MBARRIER_ARRIVE(addr) \
    asm volatile("mbarrier.arrive.shared.b64 _, [%0];" :: "r"(addr) : "memory")
#define MBARRIER_EXPECT_TX(addr, bytes) \
    asm volatile("mbarrier.arrive.expect_tx.shared.b64 _, [%0], %1;" \
                 :: "r"(addr), "r"(bytes) : "memory")
#define MBARRIER_WAIT_PARITY(addr, par) do { \
    uint32_t _m = (addr), _p = (par), _d; \
    asm volatile("{ .reg .pred p; mbarrier.try_wait.parity.acquire.cta.shared::cta.b64 p, [%1], %2;" \
                 " selp.b32 %0,1,0,p; }" : "=r"(_d) : "r"(_m), "r"(_p) : "memory"); \
    if (!_d) { \
        asm volatile("{ .reg .pred P1; WL_%=:" \
                     " mbarrier.try_wait.parity.acquire.cta.shared::cta.b64 P1, [%0], %1, 0x989680;" \
                     " @P1 bra.uni WD_%=; bra.uni WL_%=; WD_%=: }" \
                     :: "r"(_m), "r"(_p) : "memory"); \
    } \
} while (0)
#define FENCE_ASYNC() asm volatile("fence.proxy.async.shared::cta;" ::: "memory")

#define BULK_G2S(dst, src, bytes, mbar) \
    asm volatile("cp.async.bulk.shared::cluster.global.mbarrier::complete_tx::bytes " \
                 "[%0], [%1], %2, [%3];" \
                 :: "r"(dst), "l"(src), "r"(bytes), "r"(mbar) : "memory")

#define LDSM_X4(r0, r1, r2, r3, a) \
    asm volatile("ldmatrix.sync.aligned.m8n8.x4.shared.b16 {%0,%1,%2,%3}, [%4];" \
        : "=r"(r0), "=r"(r1), "=r"(r2), "=r"(r3) : "r"(a))

#define MMA16(d, a, b) \
    asm volatile("mma.sync.aligned.m16n8k16.row.col.f32.f16.f16.f32 " \
        "{%0,%1,%2,%3}, {%4,%5,%6,%7}, {%8,%9}, {%0,%1,%2,%3};" \
        : "+f"((d)[0]), "+f"((d)[1]), "+f"((d)[2]), "+f"((d)[3]) \
        : "r"((a)[0]), "r"((a)[1]), "r"((a)[2]), "r"((a)[3]), \
          "r"((b)[0]), "r"((b)[1]))

__device__ __forceinline__ ll toff(int row, int k, int kc) {
    int r = row & 127;
    int quad = ((k >> 3) & 3) ^ ((r >> 1) & 3);
    return ((ll)((row >> 7) * kc + (k >> 5)) * 128 + r) * 32 + quad * 8 + (k & 7);
}

__device__ __forceinline__ void splitw_t(__half* hp, __half* lp, int row, int k,
                                         int kc, float v) {
    ll i = toff(row, k, kc);
    __half h = __float2half_rn(v);
    hp[i] = h;
    lp[i] = __float2half_rn(v - __half2float(h));
}
__device__ __forceinline__ void splitw2_t(__half* hp, __half* lp, int row, int k,
                                          int kc, float v0, float v1) {
    ll i = toff(row, k, kc);
    __half h0 = __float2half_rn(v0), h1 = __float2half_rn(v1);
    *(__half2*)(hp + i) = __halves2half2(h0, h1);
    *(__half2*)(lp + i) = __halves2half2(
        __float2half_rn(v0 - __half2float(h0)),
        __float2half_rn(v1 - __half2float(h1)));
}
__device__ __forceinline__ void hi2_t(__half* hp, int row, int k, int kc,
                                      float v0, float v1) {
    ll i = toff(row, k, kc);
    *(__half2*)(hp + i) = __halves2half2(__float2half_rn(v0), __float2half_rn(v1));
}
__device__ __forceinline__ void splitw8_t(__half* hp, __half* lp, int row, int k,
                                          int kc, const float* f) {
    ll i = toff(row, k, kc);
    uint32_t hw[4], lw[4];
#pragma unroll
    for (int j = 0; j < 4; j++) {
        __half a = __float2half_rn(f[2*j]), b = __float2half_rn(f[2*j+1]);
        __half2 hh = __halves2half2(a, b);
        hw[j] = *(uint32_t*)&hh;
        __half2 l2 = __halves2half2(
            __float2half_rn(f[2*j]   - __half2float(a)),
            __float2half_rn(f[2*j+1] - __half2float(b)));
        lw[j] = *(uint32_t*)&l2;
    }
    *(uint4*)(hp + i) = make_uint4(hw[0], hw[1], hw[2], hw[3]);
    *(uint4*)(lp + i) = make_uint4(lw[0], lw[1], lw[2], lw[3]);
}
__device__ __forceinline__ void hi8_t(__half* hp, int row, int k, int kc,
                                      const float* f) {
    ll i = toff(row, k, kc);
    uint32_t hw[4];
#pragma unroll
    for (int j = 0; j < 4; j++) {
        __half2 hh = __halves2half2(__float2half_rn(f[2*j]),
                                    __float2half_rn(f[2*j+1]));
        hw[j] = *(uint32_t*)&hh;
    }
    *(uint4*)(hp + i) = make_uint4(hw[0], hw[1], hw[2], hw[3]);
}

struct Op { const __half* h; const __half* l; int kc; };

// ===== heavy GEMM: 128m x 256n strip, hi-only, K=64 chunks, 4-stage ring ===
// stage: Ah 2x8K@0, B0h 2x8K@16K, B1h 2x8K@32K ; stride 49152 ; 4 stages
#define HST 49152u
#define SMH 197184

__device__ __forceinline__ void chunk_mma1(
    uint32_t st, const int* ba, const int* sa2, const int* bb, const int* sb2,
    int qa, int qb, float acc[2][2][4][4])
{
#pragma unroll
    for (int kk4 = 0; kk4 < 4; kk4++) {
        const uint32_t sub = (uint32_t)(kk4 >> 1) * 8192u;
        const int kk2 = kk4 & 1;
        uint32_t ah[2][4];
#pragma unroll
        for (int tm = 0; tm < 2; tm++) {
            const uint32_t ad = st + sub + ba[tm]
                + (uint32_t)((((qa + kk2 * 2) ^ sa2[tm]) & 3) * 16);
            LDSM_X4(ah[tm][0], ah[tm][1], ah[tm][2], ah[tm][3], ad);
        }
#pragma unroll
        for (int ns = 0; ns < 2; ns++) {
            uint32_t bh[4][2];
#pragma unroll
            for (int tp = 0; tp < 2; tp++) {
                const uint32_t bd = st + 16384u + (uint32_t)ns * 16384u + sub
                    + bb[tp]
                    + (uint32_t)((((qb + kk2 * 2) ^ sb2[tp]) & 3) * 16);
                uint32_t r0, r1, r2, r3;
                LDSM_X4(r0, r1, r2, r3, bd);
                bh[2*tp][0] = r0; bh[2*tp][1] = r1;
                bh[2*tp+1][0] = r2; bh[2*tp+1][1] = r3;
            }
#pragma unroll
            for (int tm = 0; tm < 2; tm++)
#pragma unroll
                for (int tn = 0; tn < 4; tn++)
                    MMA16(acc[ns][tm][tn], ah[tm], bh[tn]);
        }
    }
}

// MODE 1: spk = (acc+bias[n])*aux[b,n] -> hi-plane only
// MODE 2: logit[m] += sum_n relu(acc+aux[b,n])*uv[b,n]
template<int MODE>
__global__ __launch_bounds__(512, 1)
void tc_gemm(Op A1, Op A2, Op B1, Op B2, int K,
             __half* __restrict__ Ch,
             int okc, const float* __restrict__ bias,
             const float* __restrict__ aux, const float* __restrict__ uv,
             float* __restrict__ logit)
{
    extern __shared__ char smem[];
    const uint32_t su = smem_u32(smem);
    const int tid = threadIdx.x;
    const int lane = tid & 31, wid = tid >> 5;
    const int wm = wid & 3, wn = wid >> 2;
    const int m0 = blockIdx.y * 128, n0 = blockIdx.x * 256;
    const int NC = K >> 6;                  // K=64 chunks
    const uint32_t mbF = su + 196608u, mbE = su + 196640u;

    if (tid == 0) {
#pragma unroll
        for (int s = 0; s < 4; s++) {
            MBARRIER_INIT(mbF + s * 8, 1);
            MBARRIER_INIT(mbE + s * 8, 16);
        }
        FENCE_ASYNC();
    }
    __syncthreads();

    auto issue = [&](int cn) {
        const int c2 = cn * 2;               // k32-chunk index (pair-aligned)
        const bool a1 = c2 < A1.kc, b1 = c2 < B1.kc;
        const __half* ah = a1 ? A1.h : A2.h;
        const __half* bh = b1 ? B1.h : B2.h;
        const int ca = a1 ? c2 : c2 - A1.kc;
        const int cb = b1 ? c2 : c2 - B1.kc;
        const int kca = a1 ? A1.kc : A2.kc;
        const int kcb = b1 ? B1.kc : B2.kc;
        const ll ao  = ((ll)((m0 >> 7) * kca + ca)) * 8192;
        const ll bo0 = ((ll)(((n0 >> 7) + 0) * kcb + cb)) * 8192;
        const ll bo1 = ((ll)(((n0 >> 7) + 1) * kcb + cb)) * 8192;
        const uint32_t st = su + (uint32_t)(cn & 3) * HST;
        const uint32_t mb = mbF + (cn & 3) * 8;
        MBARRIER_EXPECT_TX(mb, 49152u);
        BULK_G2S(st,           (const char*)ah + ao,  16384u, mb);
        BULK_G2S(st + 16384u,  (const char*)bh + bo0, 16384u, mb);
        BULK_G2S(st + 32768u,  (const char*)bh + bo1, 16384u, mb);
    };

    if (tid == 0) {
        issue(0);
        if (NC > 1) issue(1);
        if (NC > 2) issue(2);
    }

    int ba[2], sa2[2], bb[2], sb2[2];
#pragma unroll
    for (int tm = 0; tm < 2; tm++) {
        int r = wm * 32 + tm * 16 + (lane & 7) + ((lane >> 3) & 1) * 8;
        ba[tm] = r * 64; sa2[tm] = (r >> 1) & 3;
    }
#pragma unroll
    for (int tp = 0; tp < 2; tp++) {
        int r = wn * 32 + tp * 16 + (lane & 7) + (lane >> 4) * 8;
        bb[tp] = r * 64; sb2[tp] = (r >> 1) & 3;
    }
    const int qa = lane >> 4, qb = (lane >> 3) & 1;

    float acc[2][2][4][4];
#pragma unroll
    for (int s = 0; s < 2; s++)
#pragma unroll
        for (int i = 0; i < 2; i++)
#pragma unroll
            for (int j = 0; j < 4; j++)
#pragma unroll
                for (int r = 0; r < 4; r++) acc[s][i][j][r] = 0.f;

    for (int c = 0; c < NC; c++) {
        // rotating producer warp spreads issue stalls across schedulers
        if (wid == (c & 15) && lane == 0 && c + 3 < NC) {
            const int cn = c + 3;
            if (cn >= 4)
                MBARRIER_WAIT_PARITY(mbE + (cn & 3) * 8, ((cn >> 2) - 1) & 1);
            issue(cn);
        }
        MBARRIER_WAIT_PARITY(mbF + (c & 3) * 8, (c >> 2) & 1);
        chunk_mma1(su + (uint32_t)(c & 3) * HST, ba, sa2, bb, sb2, qa, qb, acc);
        if (lane == 0) MBARRIER_ARRIVE(mbE + (c & 3) * 8);
    }

    float* rowsum = (float*)(smem + 196672);
    if (MODE == 2) {
        __syncthreads();
        if (tid < 128) rowsum[tid] = 0.f;
        __syncthreads();
    }

#pragma unroll
    for (int tm = 0; tm < 2; tm++) {
        const int lr0 = wm * 32 + tm * 16 + (lane >> 2);
        const int r0 = m0 + lr0, r1 = r0 + 8;
        const int b0 = r0 / NHW, b1 = r1 / NHW;
        if (MODE == 1) {
#pragma unroll
            for (int ns = 0; ns < 2; ns++)
#pragma unroll
            for (int tn = 0; tn < 4; tn++) {
                const int gn = n0 + ns * 128 + wn * 32 + tn * 8 + (lane & 3) * 2;
                const float bb0 = bias[gn], bb1 = bias[gn + 1];
                const float* a0 = aux + (ll)b0 * 512 + gn;
                const float* a1 = aux + (ll)b1 * 512 + gn;
                hi2_t(Ch, r0, gn, okc,
                      (acc[ns][tm][tn][0] + bb0) * a0[0],
                      (acc[ns][tm][tn][1] + bb1) * a0[1]);
                hi2_t(Ch, r1, gn, okc,
                      (acc[ns][tm][tn][2] + bb0) * a1[0],
                      (acc[ns][tm][tn][3] + bb1) * a1[1]);
            }
        } else {
            float p0 = 0.f, p1 = 0.f;
#pragma unroll
            for (int ns = 0; ns < 2; ns++)
#pragma unroll
            for (int tn = 0; tn < 4; tn++) {
                const int gn = n0 + ns * 128 + wn * 32 + tn * 8 + (lane & 3) * 2;
                const float* x0 = aux + (ll)b0 * 512 + gn;
                const float* u0 = uv  + (ll)b0 * 512 + gn;
                const float* x1 = aux + (ll)b1 * 512 + gn;
                const float* u1 = uv  + (ll)b1 * 512 + gn;
                p0 += fmaxf(acc[ns][tm][tn][0] + x0[0], 0.f) * u0[0]
                    + fmaxf(acc[ns][tm][tn][1] + x0[1], 0.f) * u0[1];
                p1 += fmaxf(acc[ns][tm][tn][2] + x1[0], 0.f) * u1[0]
                    + fmaxf(acc[ns][tm][tn][3] + x1[1], 0.f) * u1[1];
            }
            p0 += __shfl_xor_sync(0xffffffffu, p0, 1);
            p0 += __shfl_xor_sync(0xffffffffu, p0, 2);
            p1 += __shfl_xor_sync(0xffffffffu, p1, 1);
            p1 += __shfl_xor_sync(0xffffffffu, p1, 2);
            if ((lane & 3) == 0) {
                atomicAdd(&rowsum[lr0], p0);
                atomicAdd(&rowsum[lr0 + 8], p1);
            }
        }
    }
    if (MODE == 2) {
        __syncthreads();
        if (tid < 128) atomicAdd(&logit[m0 + tid], rowsum[tid]);
    }
}

// ============ batched small GEMM (full precision, unchanged) ===============
struct GD {
    const __half *ah, *al; int akc;
    const __half *bh, *bl; int bkc;
    int K;
    float* C; __half* Ch; __half* Cl; int okc;
    const float* bias; int act; int atomic; int my;
};
struct GDBatch { GD d[4]; };

#define SMB 131712

__global__ __launch_bounds__(512, 1)
void tc_gemmb(GDBatch tb)
{
    const GD g = tb.d[blockIdx.z];
    if (blockIdx.y >= g.my) return;
    extern __shared__ char smem[];
    const uint32_t su = smem_u32(smem);
    const int tid = threadIdx.x;
    const int lane = tid & 31, wid = tid >> 5;
    const int wm = wid & 3, wn = wid >> 2;
    const int m0 = blockIdx.y * 128, n0 = blockIdx.x * 128;
    const int NC = g.K >> 5;
    const uint32_t mbF = su + 131072u, mbE = su + 131104u;

    if (tid == 0) {
#pragma unroll
        for (int s = 0; s < 4; s++) {
            MBARRIER_INIT(mbF + s * 8, 1);
            MBARRIER_INIT(mbE + s * 8, 16);
        }
        FENCE_ASYNC();
    }
    __syncthreads();

    auto issue = [&](int cn) {
        const ll ao = ((ll)((m0 >> 7) * g.akc + cn)) * 8192;
        const ll bo = ((ll)((n0 >> 7) * g.bkc + cn)) * 8192;
        const uint32_t st = su + (uint32_t)(cn & 3) * 32768u;
        const uint32_t mb = mbF + (cn & 3) * 8;
        MBARRIER_EXPECT_TX(mb, 32768u);
        BULK_G2S(st,           (const char*)g.ah + ao, 8192u, mb);
        BULK_G2S(st + 8192u,   (const char*)g.al + ao, 8192u, mb);
        BULK_G2S(st + 16384u,  (const char*)g.bh + bo, 8192u, mb);
        BULK_G2S(st + 24576u,  (const char*)g.bl + bo, 8192u, mb);
    };

    if (tid == 0) { issue(0); if (NC > 1) issue(1); if (NC > 2) issue(2); }

    int ba[2], sa2[2], bb[2], sb2[2];
#pragma unroll
    for (int tm = 0; tm < 2; tm++) {
        int r = wm * 32 + tm * 16 + (lane & 7) + ((lane >> 3) & 1) * 8;
        ba[tm] = r * 64; sa2[tm] = (r >> 1) & 3;
    }
#pragma unroll
    for (int tp = 0; tp < 2; tp++) {
        int r = wn * 32 + tp * 16 + (lane & 7) + (lane >> 4) * 8;
        bb[tp] = r * 64; sb2[tp] = (r >> 1) & 3;
    }
    const int qa = lane >> 4, qb = (lane >> 3) & 1;

    float acc[2][4][4];
#pragma unroll
    for (int i = 0; i < 2; i++)
#pragma unroll
        for (int j = 0; j < 4; j++)
#pragma unroll
            for (int r = 0; r < 4; r++) acc[i][j][r] = 0.f;

    for (int c = 0; c < NC; c++) {
        if (tid == 0 && c + 3 < NC) {
            const int cn = c + 3;
            if (cn >= 4)
                MBARRIER_WAIT_PARITY(mbE + (cn & 3) * 8, ((cn >> 2) - 1) & 1);
            issue(cn);
        }
        MBARRIER_WAIT_PARITY(mbF + (c & 3) * 8, (c >> 2) & 1);
        const uint32_t st = su + (uint32_t)(c & 3) * 32768u;
#pragma unroll
        for (int kk2 = 0; kk2 < 2; kk2++) {
            uint32_t ah[2][4], al[2][4], bh[4][2], bl[4][2];
#pragma unroll
            for (int tm = 0; tm < 2; tm++) {
                const uint32_t ad = st + ba[tm]
                    + (uint32_t)((((qa + kk2 * 2) ^ sa2[tm]) & 3) * 16);
                LDSM_X4(ah[tm][0], ah[tm][1], ah[tm][2], ah[tm][3], ad);
                LDSM_X4(al[tm][0], al[tm][1], al[tm][2], al[tm][3], ad + 8192u);
            }
#pragma unroll
            for (int tp = 0; tp < 2; tp++) {
                const uint32_t bd = st + 16384u + bb[tp]
                    + (uint32_t)((((qb + kk2 * 2) ^ sb2[tp]) & 3) * 16);
                uint32_t r0, r1, r2, r3;
                LDSM_X4(r0, r1, r2, r3, bd);
                bh[2*tp][0] = r0; bh[2*tp][1] = r1;
                bh[2*tp+1][0] = r2; bh[2*tp+1][1] = r3;
                LDSM_X4(r0, r1, r2, r3, bd + 8192u);
                bl[2*tp][0] = r0; bl[2*tp][1] = r1;
                bl[2*tp+1][0] = r2; bl[2*tp+1][1] = r3;
            }
#pragma unroll
            for (int tm = 0; tm < 2; tm++)
#pragma unroll
                for (int tn = 0; tn < 4; tn++) {
                    MMA16(acc[tm][tn], ah[tm], bh[tn]);
                    MMA16(acc[tm][tn], ah[tm], bl[tn]);
                    MMA16(acc[tm][tn], al[tm], bh[tn]);
                }
        }
        if (lane == 0) MBARRIER_ARRIVE(mbE + (c & 3) * 8);
    }

#pragma unroll
    for (int tm = 0; tm < 2; tm++) {
        const int lr0 = wm * 32 + tm * 16 + (lane >> 2);
        const int r0 = m0 + lr0, r1 = r0 + 8;
#pragma unroll
        for (int tn = 0; tn < 4; tn++) {
            const int gn = n0 + wn * 32 + tn * 8 + (lane & 3) * 2;
            float v0 = acc[tm][tn][0], v1 = acc[tm][tn][1];
            float v2 = acc[tm][tn][2], v3 = acc[tm][tn][3];
            if (g.bias) {
                float b0 = g.bias[gn], b1 = g.bias[gn + 1];
                v0 += b0; v1 += b1; v2 += b0; v3 += b1;
            }
            if (g.act == 1) {
                v0 = tanhf(v0); v1 = tanhf(v1);
                v2 = tanhf(v2); v3 = tanhf(v3);
            }
            if (g.atomic) {
                atomicAdd(&g.C[(ll)r0 * 512 + gn], v0);
                atomicAdd(&g.C[(ll)r0 * 512 + gn + 1], v1);
                atomicAdd(&g.C[(ll)r1 * 512 + gn], v2);
                atomicAdd(&g.C[(ll)r1 * 512 + gn + 1], v3);
            } else {
                if (g.C) {
                    *(float2*)&g.C[(ll)r0 * 512 + gn] = make_float2(v0, v1);
                    *(float2*)&g.C[(ll)r1 * 512 + gn] = make_float2(v2, v3);
                }
                if (g.Ch) {
                    splitw2_t(g.Ch, g.Cl, r0, gn, g.okc, v0, v1);
                    splitw2_t(g.Ch, g.Cl, r1, gn, g.okc, v2, v3);
                }
            }
        }
    }
}

// ===================== producers ===========================================
__global__ __launch_bounds__(256)
void transpose_k(const float* __restrict__ know, __half* __restrict__ kh)
{
    __shared__ float t[32][65];
    const int b = blockIdx.z;
    const int n0 = blockIdx.x * 32, d0 = blockIdx.y * 64;
    const int tx = threadIdx.x, ty = threadIdx.y;
#pragma unroll
    for (int r = 0; r < 8; r++) {
        int dl = ty + r * 8;
        int n = n0 + tx;
        t[tx][dl] = (n < NHW) ? know[((ll)b * ND + d0 + dl) * NHW + n] : 0.f;
    }
    __syncthreads();
    const int tid = ty * 32 + tx;
    const int nl = tid & 31, dg = tid >> 5;
    if (n0 + nl < NHW) {
        float f[8];
#pragma unroll
        for (int i = 0; i < 8; i++) f[i] = t[nl][dg * 8 + i];
        hi8_t(kh, b * NHW + n0 + nl, d0 + dg * 8, 16, f);
    }
}

struct TDesc { const float* src; __half* dh; ll E; int R; int kc; };
struct TBatch { TDesc d[9]; };

__global__ __launch_bounds__(256)
void trans_w(TBatch tb)
{
    const TDesc td = tb.d[blockIdx.z];
    const int k0 = blockIdx.y * 64, n0 = blockIdx.x * 32;
    if (k0 >= td.R) return;
    __half* dl = td.dh + td.E;
    __shared__ float t[32][65];
    const int tx = threadIdx.x, ty = threadIdx.y;
#pragma unroll
    for (int r = 0; r < 8; r++) {
        int kk = ty + r * 8;
        t[tx][kk] = td.src[(ll)(k0 + kk) * 512 + n0 + tx];
    }
    __syncthreads();
    const int tid = ty * 32 + tx;
    const int nl = tid & 31, kg = tid >> 5;
    float f[8];
#pragma unroll
    for (int i = 0; i < 8; i++) f[i] = t[nl][kg * 8 + i];
    splitw8_t(td.dh, dl, n0 + nl, k0 + kg * 8, td.kc, f);
}

__global__ void wsumT_kernel(const float* __restrict__ Wwcat,
                             __half* __restrict__ nh)
{
    int g = blockIdx.x * 256 + threadIdx.x;
    int n = g >> 6, k = (g & 63) * 8;
    float f[8];
#pragma unroll
    for (int i = 0; i < 8; i++)
        f[i] = Wwcat[(ll)(512 + k + i) * 512 + n] + Wwcat[(ll)(1024 + k + i) * 512 + n];
    splitw8_t(nh, nh + 524288, n, 512 + k, 32, f);
}

__global__ void bias2_kernel(const float* __restrict__ Wc1, const float* __restrict__ bk,
                             const float* __restrict__ bc1, float* __restrict__ b2)
{
    int d = blockIdx.x * 256 + threadIdx.x;
    int e0 = blockIdx.y * 32;
    float acc = (blockIdx.y == 0) ? bc1[d] : 0.f;
#pragma unroll
    for (int e = 0; e < 32; e++)
        acc += bk[e0 + e] * Wc1[(ll)(512 + e0 + e) * 512 + d];
    atomicAdd(&b2[d], acc);
}

__global__ void init_bufs(const float* __restrict__ bwcat,
                          char* __restrict__ Sb, float* __restrict__ outM)
{
    int i = blockIdx.x * 256 + threadIdx.x;
    ((float*)(Sb + B_QF))[i] = 0.f;
    ((float*)(Sb + B_CQ))[i] = 0.f;
    if (i < NM) ((float*)(Sb + B_LOGIT))[i] = 0.f;
    if (i < 512) ((float*)(Sb + B_BIAS2))[i] = 0.f;
    outM[i] = bwcat[i & 511];
}

__global__ void tanhsplit_kernel(const float* __restrict__ qf,
                                 const float* __restrict__ bsc,
                                 __half* __restrict__ qh)
{
    int g = blockIdx.x * 256 + threadIdx.x;
    int row = g >> 6, k = (g & 63) * 8;
    float f[8];
#pragma unroll
    for (int i = 0; i < 8; i++)
        f[i] = tanhf(qf[(ll)row * 512 + k + i] + bsc[k + i]);
    splitw8_t(qh, qh + 131072, row, k, 16, f);
}

__global__ void copy_split(const float* __restrict__ q, const float* __restrict__ c0,
                           const float* __restrict__ m0, const float* __restrict__ wc2,
                           const float* __restrict__ wk,
                           char* __restrict__ Sb)
{
    int g = blockIdx.x * 256 + threadIdx.x;
    const float* src; __half* h; ll E; int ld, kc, j;
    if (g < 32768)       { src = q;   h = (__half*)(Sb + B_QR);   E = 262144; ld = 1024; kc = 32; j = g; }
    else if (g < 49152)  { src = c0;  h = (__half*)(Sb + B_C0R);  E = 131072; ld = 512;  kc = 16; j = g - 32768; }
    else if (g < 65536)  { src = m0;  h = (__half*)(Sb + B_M0R);  E = 131072; ld = 512;  kc = 16; j = g - 49152; }
    else if (g < 98304)  { src = wc2; h = (__half*)(Sb + B_WC2R); E = 262144; ld = 512;  kc = 16; j = g - 65536; }
    else                 { src = wk;  h = (__half*)(Sb + B_WKP);  E = 262144; ld = 512;  kc = 16; j = g - 98304; }
    const int gpr = ld >> 3;
    int row = j / gpr, k = (j % gpr) * 8;
    float f[8];
    const float* s = src + (ll)row * ld + k;
#pragma unroll
    for (int i = 0; i < 8; i++) f[i] = s[i];
    splitw8_t(h, h + E, row, k, kc, f);
}

__global__ __launch_bounds__(256)
void attnc_kernel(const float* __restrict__ words, const float* __restrict__ cq,
                  const float* __restrict__ bcq,
                  const float* __restrict__ wac, const float* __restrict__ bac,
                  float* __restrict__ control)
{
    const int b = blockIdx.x, tid = threadIdx.x;
    const int warp = tid >> 5, lane = tid & 31;
    __shared__ float cw[ND];
    __shared__ float sa[NS];
    for (int d = tid; d < ND; d += 256)
        cw[d] = (cq[(ll)b * ND + d] + bcq[d]) * wac[d];
    __syncthreads();
#pragma unroll
    for (int r = 0; r < 4; r++) {
        int s = warp * 4 + r;
        const float* wp = words + ((ll)b * NS + s) * ND;
        float acc = 0.f;
        for (int d = lane; d < ND; d += 32) acc += cw[d] * wp[d];
#pragma unroll
        for (int o = 16; o; o >>= 1) acc += __shfl_xor_sync(0xffffffffu, acc, o);
        if (lane == 0) sa[s] = acc + bac[0];
    }
    __syncthreads();
    if (warp == 0) {
        float v = sa[lane], mx = v;
#pragma unroll
        for (int o = 16; o; o >>= 1) mx = fmaxf(mx, __shfl_xor_sync(0xffffffffu, mx, o));
        float e = expf(v - mx), sm = e;
#pragma unroll
        for (int o = 16; o; o >>= 1) sm += __shfl_xor_sync(0xffffffffu, sm, o);
        sa[lane] = e / sm;
    }
    __syncthreads();
    for (int d = tid; d < ND; d += 256) {
        float acc = 0.f;
#pragma unroll 8
        for (int s = 0; s < NS; s++) acc += sa[s] * words[((ll)b * NS + s) * ND + d];
        control[(ll)b * ND + d] = acc;
    }
}

__global__ void vsplit_kernel(const float* __restrict__ control,
                              const float* __restrict__ war,
                              __half* __restrict__ vh)
{
    int g = blockIdx.x * 256 + threadIdx.x;
    int b = g >> 6, k = (g & 63) * 8;
    float f[8];
#pragma unroll
    for (int i = 0; i < 8; i++)
        f[i] = control[(ll)b * 512 + k + i] * war[k + i];
    splitw8_t(vh, vh + 131072, b, k, 16, f);
}

__global__ __launch_bounds__(256)
void softmaxn_kernel(const float* __restrict__ logit, float* __restrict__ ar)
{
    const int b = blockIdx.x, tid = threadIdx.x;
    __shared__ float s[256];
    float v = (tid < NHW) ? logit[(ll)b * NHW + tid] : -1e30f;
    s[tid] = v; __syncthreads();
    for (int o = 128; o; o >>= 1) { if (tid < o) s[tid] = fmaxf(s[tid], s[tid + o]); __syncthreads(); }
    float mx = s[0]; __syncthreads();
    float e = (tid < NHW) ? expf(v - mx) : 0.f;
    s[tid] = e; __syncthreads();
    for (int o = 128; o; o >>= 1) { if (tid < o) s[tid] += s[tid + o]; __syncthreads(); }
    float sum = s[0];
    if (tid < NHW) ar[(ll)b * NHW + tid] = e / sum;
}

__global__ __launch_bounds__(256)
void read_kernel(const float* __restrict__ know, const float* __restrict__ ar,
                 __half* __restrict__ rh)
{
    const int b = blockIdx.x, tid = threadIdx.x;
    const int warp = tid >> 5, lane = tid & 31;
    __shared__ float s[NHW];
    if (tid < NHW) s[tid] = ar[(ll)b * NHW + tid];
    __syncthreads();
    for (int d = warp; d < ND; d += 8) {
        const float* kp = know + ((ll)b * ND + d) * NHW;
        float acc = 0.f;
        for (int n = lane; n < NHW; n += 32) acc += kp[n] * s[n];
#pragma unroll
        for (int o = 16; o; o >>= 1) acc += __shfl_xor_sync(0xffffffffu, acc, o);
        if (lane == 0) splitw_t(rh, rh + 131072, b, d, 16, acc);
    }
}

// ===========================================================================
extern "C" void kernel_launch(void* const* d_in, const int* in_sizes, int n_in,
                              void* d_out, int out_size)
{
    const float* words    = (const float*)d_in[0];
    const float* question = (const float*)d_in[1];
    const float* know     = (const float*)d_in[2];
    const float* control0 = (const float*)d_in[3];
    const float* memory0  = (const float*)d_in[4];
    const float* Wsc  = (const float*)d_in[5];
    const float* bsc  = (const float*)d_in[6];
    const float* Wp   = (const float*)d_in[7];
    const float* bp   = (const float*)d_in[8];
    const float* Wcq  = (const float*)d_in[9];
    const float* bcq  = (const float*)d_in[10];
    const float* wac  = (const float*)d_in[11];
    const float* bac  = (const float*)d_in[12];
    const float* Wm   = (const float*)d_in[13];
    const float* bm   = (const float*)d_in[14];
    const float* Wk   = (const float*)d_in[15];
    const float* bk   = (const float*)d_in[16];
    const float* Wc1  = (const float*)d_in[17];
    const float* bc1  = (const float*)d_in[18];
    const float* Wc2  = (const float*)d_in[19];
    const float* war  = (const float*)d_in[21];
    const float* Wwcat = (const float*)d_in[27];
    const float* bwcat = (const float*)d_in[28];

    cudaFuncSetAttribute(tc_gemm<1>, cudaFuncAttributeMaxDynamicSharedMemorySize, SMH);
    cudaFuncSetAttribute(tc_gemm<2>, cudaFuncAttributeMaxDynamicSharedMemorySize, SMH);
    cudaFuncSetAttribute(tc_gemmb, cudaFuncAttributeMaxDynamicSharedMemorySize, SMB);

    char* Sb = nullptr;
    cudaGetSymbolAddress((void**)&Sb, g_s);

    float* outC = (float*)d_out;
    float* outM = (float*)d_out + (ll)NB * ND;

    auto F  = [&](ll off) { return (float*)(Sb + off); };
    auto Hh = [&](ll off) { return (__half*)(Sb + off); };
    Op KNOWT = { Hh(B_KNOWT), nullptr, 16 };
    Op SPK   = { Hh(B_SPK),   nullptr, 16 };
    Op WKT_H = { Hh(B_WKT),   nullptr, 16 };
    Op W1A_H = { Hh(B_W1AT),  nullptr, 16 };
    Op WKW_H = { Hh(B_WKWT),  nullptr, 16 };
    Op Z = { nullptr, nullptr, 0 };

    init_bufs<<<512, 256>>>(bwcat, Sb, outM);
    {
        TBatch tb;
        tb.d[0] = { Wk,                     Hh(B_WKT),   262144, 512, 16 };
        tb.d[1] = { Wc1,                    Hh(B_W1AT),  262144, 512, 16 };
        tb.d[2] = { Wc1 + (ll)ND * ND,      Hh(B_W1BT),  262144, 512, 16 };
        tb.d[3] = { Wsc,                    Hh(B_WSCT),  524288, 1024, 32 };
        tb.d[4] = { Wp,                     Hh(B_WPT),   262144, 512, 16 };
        tb.d[5] = { Wcq,                    Hh(B_WCQT),  524288, 1024, 32 };
        tb.d[6] = { Wm,                     Hh(B_WMT),   262144, 512, 16 };
        tb.d[7] = { Wc1 + (ll)2 * ND * ND,  Hh(B_WC1CT), 262144, 512, 16 };
        tb.d[8] = { Wwcat,                  Hh(B_NMBT),  524288, 512, 32 };
        trans_w<<<dim3(16, 16, 9), dim3(32, 8)>>>(tb);
    }
    transpose_k<<<dim3(7, 8, NB), dim3(32, 8)>>>(know, Hh(B_KNOWT));
    copy_split<<<512, 256>>>(question, control0, memory0, Wc2, Wk, Sb);

    const ll CH16 = 16 * 4096;

    // batch1: q-half1, q-half2 (split-K atomic), pm, WkW1b
    {
        GDBatch b{};
        b.d[0] = { Hh(B_QR), Hh(B_QR) + 262144, 32,
                   Hh(B_WSCT), Hh(B_WSCT) + 524288, 32,
                   512, F(B_QF), nullptr, nullptr, 0, nullptr, 0, 1, 2 };
        b.d[1] = { Hh(B_QR) + CH16, Hh(B_QR) + 262144 + CH16, 32,
                   Hh(B_WSCT) + CH16, Hh(B_WSCT) + 524288 + CH16, 32,
                   512, F(B_QF), nullptr, nullptr, 0, nullptr, 0, 1, 2 };
        b.d[2] = { Hh(B_M0R), Hh(B_M0R) + 131072, 16,
                   Hh(B_WMT), Hh(B_WMT) + 262144, 16,
                   512, F(B_PMF), Hh(B_PMP), Hh(B_PMP) + 131072, 16, bm, 0, 0, 2 };
        b.d[3] = { Hh(B_W1BT), Hh(B_W1BT) + 262144, 16,
                   Hh(B_WKP), Hh(B_WKP) + 262144, 16,
                   512, nullptr, Hh(B_WKWT), Hh(B_WKWT) + 262144, 16,
                   nullptr, 0, 0, 4 };
        tc_gemmb<<<dim3(4, 4, 4), 512, SMB>>>(b);
    }

    // HEAVY 1: spk = (knowT_hi @ Wk_hi + bk) * pm[b] -> hi-plane
    tc_gemm<1><<<dim3(2, NM / 128), 512, SMH>>>(
        KNOWT, Z, WKT_H, Z, 512,
        Hh(B_SPK), 16, bk,
        F(B_PMF), nullptr, nullptr);

    wsumT_kernel<<<128, 256>>>(Wwcat, Hh(B_NMBT));
    bias2_kernel<<<dim3(2, 16), 256>>>(Wc1, bk, bc1, F(B_BIAS2));
    tanhsplit_kernel<<<64, 256>>>(F(B_QF), bsc, Hh(B_Q));

    // batch2: pa, pmc
    {
        GDBatch b{};
        b.d[0] = { Hh(B_Q), Hh(B_Q) + 131072, 16,
                   Hh(B_WPT), Hh(B_WPT) + 262144, 16,
                   512, nullptr, Hh(B_PA), Hh(B_PA) + 131072, 16, bp, 0, 0, 2 };
        b.d[1] = { Hh(B_PMP), Hh(B_PMP) + 131072, 16,
                   Hh(B_WC1CT), Hh(B_WC1CT) + 262144, 16,
                   512, F(B_PMC), nullptr, nullptr, 0, F(B_BIAS2), 0, 0, 2 };
        tc_gemmb<<<dim3(4, 2, 2), 512, SMB>>>(b);
    }
    // cq split-K batch
    {
        GDBatch b{};
        b.d[0] = { Hh(B_C0R), Hh(B_C0R) + 131072, 16,
                   Hh(B_WCQT), Hh(B_WCQT) + 524288, 32,
                   512, F(B_CQ), nullptr, nullptr, 0, nullptr, 0, 1, 2 };
        b.d[1] = { Hh(B_PA), Hh(B_PA) + 131072, 16,
                   Hh(B_WCQT) + CH16, Hh(B_WCQT) + 524288 + CH16, 32,
                   512, F(B_CQ), nullptr, nullptr, 0, nullptr, 0, 1, 2 };
        tc_gemmb<<<dim3(4, 2, 2), 512, SMB>>>(b);
    }
    attnc_kernel<<<NB, 256>>>(words, F(B_CQ), bcq, wac, bac, outC);
    vsplit_kernel<<<64, 256>>>(outC, war, Hh(B_V));
    {
        GDBatch b{};
        b.d[0] = { Hh(B_V), Hh(B_V) + 131072, 16,
                   Hh(B_WC2R), Hh(B_WC2R) + 262144, 16,
                   512, F(B_U), nullptr, nullptr, 0, nullptr, 0, 0, 2 };
        tc_gemmb<<<dim3(4, 2, 1), 512, SMB>>>(b);
    }
    // HEAVY 2: logit += relu(spk_hi@W1a_hi + knowT_hi@WkW_hi + pmc).u
    tc_gemm<2><<<dim3(2, NM / 128), 512, SMH>>>(
        SPK, KNOWT, W1A_H, WKW_H, 1024,
        nullptr, 16, nullptr,
        F(B_PMC), F(B_U), F(B_LOGIT));

    softmaxn_kernel<<<NB, 256>>>(F(B_LOGIT), F(B_AR));
    read_kernel<<<NB, 256>>>(know, F(B_AR), Hh(B_READ));

    // next_mem split-K batch
    {
        GDBatch b{};
        b.d[0] = { Hh(B_READ), Hh(B_READ) + 131072, 16,
                   Hh(B_NMBT), Hh(B_NMBT) + 524288, 32,
                   512, outM, nullptr, nullptr, 0, nullptr, 0, 1, 2 };
        b.d[1] = { Hh(B_M0R), Hh(B_M0R) + 131072, 16,
                   Hh(B_NMBT) + CH16, Hh(B_NMBT) + 524288 + CH16, 32,
                   512, outM, nullptr, nullptr, 0, nullptr, 0, 1, 2 };
        tc_gemmb<<<dim3(4, 2, 2), 512, SMB>>>(b);
    }
}

// round 17
// speedup vs baseline: 1.3783x; 1.0136x over previous
#include <cuda_runtime.h>
#include <cuda_fp16.h>
#include <cstdint>

typedef long long ll;

#define NB 256
#define NS 32
#define ND 512
#define NHW 196
#define NM (NB*NHW)   // 50176

// --------------------- scratch layout (BYTE offsets) ----------------------
#define B_Q      ((ll)0)
#define B_PA     ((ll)524288)
#define B_CQ     ((ll)1048576)
#define B_PMP    ((ll)1572864)
#define B_PMF    ((ll)2097152)
#define B_PMC    ((ll)2621440)
#define B_V      ((ll)3145728)
#define B_U      ((ll)3670016)
#define B_READ   ((ll)4194304)
#define B_BIAS2  ((ll)4719616)
#define B_LOGIT  ((ll)4721664)
#define B_AR     ((ll)4922368)
#define B_WKT    ((ll)5242880)
#define B_W1AT   ((ll)6291456)
#define B_WKWT   ((ll)7340032)
#define B_WSCT   ((ll)8388608)
#define B_WPT    ((ll)10485760)
#define B_WCQT   ((ll)11534336)
#define B_WMT    ((ll)13631488)
#define B_WC1CT  ((ll)14680064)
#define B_NMBT   ((ll)15728640)
#define B_W1BT   ((ll)17825792)
#define B_QR     ((ll)18874368)
#define B_C0R    ((ll)19922944)
#define B_M0R    ((ll)20447232)
#define B_WC2R   ((ll)20971520)
#define B_KNOWT  ((ll)22020096)    // hi-ONLY plane E=25690112
#define B_SPK    ((ll)124780544)   // hi-ONLY plane E=25690112
#define B_WKP    ((ll)227540992)
#define B_QF     ((ll)228589568)
#define B_TOTAL  ((ll)229113856)

__device__ __align__(1024) char g_s[B_TOTAL];

// ===================== arch-generic PTX helpers ============================
__device__ __forceinline__ uint32_t smem_u32(const void* p) {
    uint32_t a;
    asm("{ .reg .u64 t; cvta.to.shared.u64 t, %1; cvt.u32.u64 %0, t; }"
        : "=r"(a) : "l"(p));
    return a;
}

#define MBARRIER_INIT(addr, cnt) \
    asm volatile("mbarrier.init.shared.b64 [%0], %1;" :: "r"(addr), "r"(cnt) : "memory")
#define MBARRIER_ARRIVE(addr) \
    asm volatile("mbarrier.arrive.shared.b64 _, [%0];" :: "r"(addr) : "memory")
#define MBARRIER_EXPECT_TX(addr, bytes) \
    asm volatile("mbarrier.arrive.expect_tx.shared.b64 _, [%0], %1;" \
                 :: "r"(addr), "r"(bytes) : "memory")
#define MBARRIER_WAIT_PARITY(addr, par) do { \
    uint32_t _m = (addr), _p = (par), _d; \
    asm volatile("{ .reg .pred p; mbarrier.try_wait.parity.acquire.cta.shared::cta.b64 p, [%1], %2;" \
                 " selp.b32 %0,1,0,p; }" : "=r"(_d) : "r"(_m), "r"(_p) : "memory"); \
    if (!_d) { \
        asm volatile("{ .reg .pred P1; WL_%=:" \
                     " mbarrier.try_wait.parity.acquire.cta.shared::cta.b64 P1, [%0], %1, 0x989680;" \
                     " @P1 bra.uni WD_%=; bra.uni WL_%=; WD_%=: }" \
                     :: "r"(_m), "r"(_p) : "memory"); \
    } \
} while (0)
#define FENCE_ASYNC() asm volatile("fence.proxy.async.shared::cta;" ::: "memory")

#define BULK_G2S(dst, src, bytes, mbar) \
    asm volatile("cp.async.bulk.shared::cluster.global.mbarrier::complete_tx::bytes " \
                 "[%0], [%1], %2, [%3];" \
                 :: "r"(dst), "l"(src), "r"(bytes), "r"(mbar) : "memory")

#define LDSM_X4(r0, r1, r2, r3, a) \
    asm volatile("ldmatrix.sync.aligned.m8n8.x4.shared.b16 {%0,%1,%2,%3}, [%4];" \
        : "=r"(r0), "=r"(r1), "=r"(r2), "=r"(r3) : "r"(a))

#define MMA16(d, a, b) \
    asm volatile("mma.sync.aligned.m16n8k16.row.col.f32.f16.f16.f32 " \
        "{%0,%1,%2,%3}, {%4,%5,%6,%7}, {%8,%9}, {%0,%1,%2,%3};" \
        : "+f"((d)[0]), "+f"((d)[1]), "+f"((d)[2]), "+f"((d)[3]) \
        : "r"((a)[0]), "r"((a)[1]), "r"((a)[2]), "r"((a)[3]), \
          "r"((b)[0]), "r"((b)[1]))

__device__ __forceinline__ ll toff(int row, int k, int kc) {
    int r = row & 127;
    int quad = ((k >> 3) & 3) ^ ((r >> 1) & 3);
    return ((ll)((row >> 7) * kc + (k >> 5)) * 128 + r) * 32 + quad * 8 + (k & 7);
}

__device__ __forceinline__ void splitw_t(__half* hp, __half* lp, int row, int k,
                                         int kc, float v) {
    ll i = toff(row, k, kc);
    __half h = __float2half_rn(v);
    hp[i] = h;
    lp[i] = __float2half_rn(v - __half2float(h));
}
__device__ __forceinline__ void splitw2_t(__half* hp, __half* lp, int row, int k,
                                          int kc, float v0, float v1) {
    ll i = toff(row, k, kc);
    __half h0 = __float2half_rn(v0), h1 = __float2half_rn(v1);
    *(__half2*)(hp + i) = __halves2half2(h0, h1);
    *(__half2*)(lp + i) = __halves2half2(
        __float2half_rn(v0 - __half2float(h0)),
        __float2half_rn(v1 - __half2float(h1)));
}
__device__ __forceinline__ void hi2_t(__half* hp, int row, int k, int kc,
                                      float v0, float v1) {
    ll i = toff(row, k, kc);
    *(__half2*)(hp + i) = __halves2half2(__float2half_rn(v0), __float2half_rn(v1));
}
__device__ __forceinline__ void splitw8_t(__half* hp, __half* lp, int row, int k,
                                          int kc, const float* f) {
    ll i = toff(row, k, kc);
    uint32_t hw[4], lw[4];
#pragma unroll
    for (int j = 0; j < 4; j++) {
        __half a = __float2half_rn(f[2*j]), b = __float2half_rn(f[2*j+1]);
        __half2 hh = __halves2half2(a, b);
        hw[j] = *(uint32_t*)&hh;
        __half2 l2 = __halves2half2(
            __float2half_rn(f[2*j]   - __half2float(a)),
            __float2half_rn(f[2*j+1] - __half2float(b)));
        lw[j] = *(uint32_t*)&l2;
    }
    *(uint4*)(hp + i) = make_uint4(hw[0], hw[1], hw[2], hw[3]);
    *(uint4*)(lp + i) = make_uint4(lw[0], lw[1], lw[2], lw[3]);
}
__device__ __forceinline__ void hi8_t(__half* hp, int row, int k, int kc,
                                      const float* f) {
    ll i = toff(row, k, kc);
    uint32_t hw[4];
#pragma unroll
    for (int j = 0; j < 4; j++) {
        __half2 hh = __halves2half2(__float2half_rn(f[2*j]),
                                    __float2half_rn(f[2*j+1]));
        hw[j] = *(uint32_t*)&hh;
    }
    *(uint4*)(hp + i) = make_uint4(hw[0], hw[1], hw[2], hw[3]);
}

struct Op { const __half* h; const __half* l; int kc; };

// ===== heavy GEMM: 128m x 256n strip, hi-only, K=64 chunks, 4-stage ring ===
// stage: Ah 2x8K@0, B0h 2x8K@16K, B1h 2x8K@32K ; stride 49152 ; 4 stages
#define HST 49152u
#define SMH 197184

__device__ __forceinline__ void chunk_mma1(
    uint32_t st, const int* ba, const int* sa2, const int* bb, const int* sb2,
    int qa, int qb, float acc[2][2][4][4])
{
#pragma unroll
    for (int kk4 = 0; kk4 < 4; kk4++) {
        const uint32_t sub = (uint32_t)(kk4 >> 1) * 8192u;
        const int kk2 = kk4 & 1;
        uint32_t ah[2][4];
#pragma unroll
        for (int tm = 0; tm < 2; tm++) {
            const uint32_t ad = st + sub + ba[tm]
                + (uint32_t)((((qa + kk2 * 2) ^ sa2[tm]) & 3) * 16);
            LDSM_X4(ah[tm][0], ah[tm][1], ah[tm][2], ah[tm][3], ad);
        }
#pragma unroll
        for (int ns = 0; ns < 2; ns++) {
            uint32_t bh[4][2];
#pragma unroll
            for (int tp = 0; tp < 2; tp++) {
                const uint32_t bd = st + 16384u + (uint32_t)ns * 16384u + sub
                    + bb[tp]
                    + (uint32_t)((((qb + kk2 * 2) ^ sb2[tp]) & 3) * 16);
                uint32_t r0, r1, r2, r3;
                LDSM_X4(r0, r1, r2, r3, bd);
                bh[2*tp][0] = r0; bh[2*tp][1] = r1;
                bh[2*tp+1][0] = r2; bh[2*tp+1][1] = r3;
            }
#pragma unroll
            for (int tm = 0; tm < 2; tm++)
#pragma unroll
                for (int tn = 0; tn < 4; tn++)
                    MMA16(acc[ns][tm][tn], ah[tm], bh[tn]);
        }
    }
}

// MODE 1: spk = (acc+bias[n])*aux[b,n] -> hi-plane only
// MODE 2: logit[m] += sum_n relu(acc+aux[b,n])*uv[b,n]
template<int MODE>
__global__ __launch_bounds__(512, 1)
void tc_gemm(Op A1, Op A2, Op B1, Op B2, int K,
             __half* __restrict__ Ch,
             int okc, const float* __restrict__ bias,
             const float* __restrict__ aux, const float* __restrict__ uv,
             float* __restrict__ logit)
{
    extern __shared__ char smem[];
    const uint32_t su = smem_u32(smem);
    const int tid = threadIdx.x;
    const int lane = tid & 31, wid = tid >> 5;
    const int wm = wid & 3, wn = wid >> 2;
    const int m0 = blockIdx.y * 128, n0 = blockIdx.x * 256;
    const int NC = K >> 6;
    const uint32_t mbF = su + 196608u, mbE = su + 196640u;

    if (tid == 0) {
#pragma unroll
        for (int s = 0; s < 4; s++) {
            MBARRIER_INIT(mbF + s * 8, 1);
            MBARRIER_INIT(mbE + s * 8, 16);
        }
        FENCE_ASYNC();
    }
    __syncthreads();

    auto issue = [&](int cn) {
        const int c2 = cn * 2;
        const bool a1 = c2 < A1.kc, b1 = c2 < B1.kc;
        const __half* ah = a1 ? A1.h : A2.h;
        const __half* bh = b1 ? B1.h : B2.h;
        const int ca = a1 ? c2 : c2 - A1.kc;
        const int cb = b1 ? c2 : c2 - B1.kc;
        const int kca = a1 ? A1.kc : A2.kc;
        const int kcb = b1 ? B1.kc : B2.kc;
        const ll ao  = ((ll)((m0 >> 7) * kca + ca)) * 8192;
        const ll bo0 = ((ll)(((n0 >> 7) + 0) * kcb + cb)) * 8192;
        const ll bo1 = ((ll)(((n0 >> 7) + 1) * kcb + cb)) * 8192;
        const uint32_t st = su + (uint32_t)(cn & 3) * HST;
        const uint32_t mb = mbF + (cn & 3) * 8;
        MBARRIER_EXPECT_TX(mb, 49152u);
        BULK_G2S(st,           (const char*)ah + ao,  16384u, mb);
        BULK_G2S(st + 16384u,  (const char*)bh + bo0, 16384u, mb);
        BULK_G2S(st + 32768u,  (const char*)bh + bo1, 16384u, mb);
    };

    if (tid == 0) {
        issue(0);
        if (NC > 1) issue(1);
        if (NC > 2) issue(2);
    }

    int ba[2], sa2[2], bb[2], sb2[2];
#pragma unroll
    for (int tm = 0; tm < 2; tm++) {
        int r = wm * 32 + tm * 16 + (lane & 7) + ((lane >> 3) & 1) * 8;
        ba[tm] = r * 64; sa2[tm] = (r >> 1) & 3;
    }
#pragma unroll
    for (int tp = 0; tp < 2; tp++) {
        int r = wn * 32 + tp * 16 + (lane & 7) + (lane >> 4) * 8;
        bb[tp] = r * 64; sb2[tp] = (r >> 1) & 3;
    }
    const int qa = lane >> 4, qb = (lane >> 3) & 1;

    float acc[2][2][4][4];
#pragma unroll
    for (int s = 0; s < 2; s++)
#pragma unroll
        for (int i = 0; i < 2; i++)
#pragma unroll
            for (int j = 0; j < 4; j++)
#pragma unroll
                for (int r = 0; r < 4; r++) acc[s][i][j][r] = 0.f;

    for (int c = 0; c < NC; c++) {
        if (wid == (c & 15) && lane == 0 && c + 3 < NC) {
            const int cn = c + 3;
            if (cn >= 4)
                MBARRIER_WAIT_PARITY(mbE + (cn & 3) * 8, ((cn >> 2) - 1) & 1);
            issue(cn);
        }
        MBARRIER_WAIT_PARITY(mbF + (c & 3) * 8, (c >> 2) & 1);
        chunk_mma1(su + (uint32_t)(c & 3) * HST, ba, sa2, bb, sb2, qa, qb, acc);
        if (lane == 0) MBARRIER_ARRIVE(mbE + (c & 3) * 8);
    }

    float* rowsum = (float*)(smem + 196672);
    if (MODE == 2) {
        __syncthreads();
        if (tid < 128) rowsum[tid] = 0.f;
        __syncthreads();
    }

#pragma unroll
    for (int tm = 0; tm < 2; tm++) {
        const int lr0 = wm * 32 + tm * 16 + (lane >> 2);
        const int r0 = m0 + lr0, r1 = r0 + 8;
        const int b0 = r0 / NHW, b1 = r1 / NHW;
        if (MODE == 1) {
#pragma unroll
            for (int ns = 0; ns < 2; ns++)
#pragma unroll
            for (int tn = 0; tn < 4; tn++) {
                const int gn = n0 + ns * 128 + wn * 32 + tn * 8 + (lane & 3) * 2;
                const float bb0 = bias[gn], bb1 = bias[gn + 1];
                const float* a0 = aux + (ll)b0 * 512 + gn;
                const float* a1 = aux + (ll)b1 * 512 + gn;
                hi2_t(Ch, r0, gn, okc,
                      (acc[ns][tm][tn][0] + bb0) * a0[0],
                      (acc[ns][tm][tn][1] + bb1) * a0[1]);
                hi2_t(Ch, r1, gn, okc,
                      (acc[ns][tm][tn][2] + bb0) * a1[0],
                      (acc[ns][tm][tn][3] + bb1) * a1[1]);
            }
        } else {
            float p0 = 0.f, p1 = 0.f;
#pragma unroll
            for (int ns = 0; ns < 2; ns++)
#pragma unroll
            for (int tn = 0; tn < 4; tn++) {
                const int gn = n0 + ns * 128 + wn * 32 + tn * 8 + (lane & 3) * 2;
                const float* x0 = aux + (ll)b0 * 512 + gn;
                const float* u0 = uv  + (ll)b0 * 512 + gn;
                const float* x1 = aux + (ll)b1 * 512 + gn;
                const float* u1 = uv  + (ll)b1 * 512 + gn;
                p0 += fmaxf(acc[ns][tm][tn][0] + x0[0], 0.f) * u0[0]
                    + fmaxf(acc[ns][tm][tn][1] + x0[1], 0.f) * u0[1];
                p1 += fmaxf(acc[ns][tm][tn][2] + x1[0], 0.f) * u1[0]
                    + fmaxf(acc[ns][tm][tn][3] + x1[1], 0.f) * u1[1];
            }
            p0 += __shfl_xor_sync(0xffffffffu, p0, 1);
            p0 += __shfl_xor_sync(0xffffffffu, p0, 2);
            p1 += __shfl_xor_sync(0xffffffffu, p1, 1);
            p1 += __shfl_xor_sync(0xffffffffu, p1, 2);
            if ((lane & 3) == 0) {
                atomicAdd(&rowsum[lr0], p0);
                atomicAdd(&rowsum[lr0 + 8], p1);
            }
        }
    }
    if (MODE == 2) {
        __syncthreads();
        if (tid < 128) atomicAdd(&logit[m0 + tid], rowsum[tid]);
    }
}

// ======= batched small GEMM (full precision, K=64 chunks, 3-stage ring) ====
// stage: Ah 16K@0, Al 16K@16K, Bh 16K@32K, Bl 16K@48K ; stride 65536
struct GD {
    const __half *ah, *al; int akc;
    const __half *bh, *bl; int bkc;
    int K;
    float* C; __half* Ch; __half* Cl; int okc;
    const float* bias; int act; int atomic; int my;
};
struct GDBatch { GD d[4]; };

#define SSTG 65536u
#define SMB 196736

__global__ __launch_bounds__(512, 1)
void tc_gemmb(GDBatch tb)
{
    const GD g = tb.d[blockIdx.z];
    if (blockIdx.y >= g.my) return;
    extern __shared__ char smem[];
    const uint32_t su = smem_u32(smem);
    const int tid = threadIdx.x;
    const int lane = tid & 31, wid = tid >> 5;
    const int wm = wid & 3, wn = wid >> 2;
    const int m0 = blockIdx.y * 128, n0 = blockIdx.x * 128;
    const int NC = g.K >> 6;
    const uint32_t mbF = su + 196608u, mbE = su + 196640u;

    if (tid == 0) {
#pragma unroll
        for (int s = 0; s < 3; s++) {
            MBARRIER_INIT(mbF + s * 8, 1);
            MBARRIER_INIT(mbE + s * 8, 16);
        }
        FENCE_ASYNC();
    }
    __syncthreads();

    auto issue = [&](int cn) {
        const int c2 = cn * 2;
        const ll ao = ((ll)((m0 >> 7) * g.akc + c2)) * 8192;
        const ll bo = ((ll)((n0 >> 7) * g.bkc + c2)) * 8192;
        const uint32_t st = su + (uint32_t)(cn % 3) * SSTG;
        const uint32_t mb = mbF + (cn % 3) * 8;
        MBARRIER_EXPECT_TX(mb, 65536u);
        BULK_G2S(st,           (const char*)g.ah + ao, 16384u, mb);
        BULK_G2S(st + 16384u,  (const char*)g.al + ao, 16384u, mb);
        BULK_G2S(st + 32768u,  (const char*)g.bh + bo, 16384u, mb);
        BULK_G2S(st + 49152u,  (const char*)g.bl + bo, 16384u, mb);
    };

    if (tid == 0) { issue(0); if (NC > 1) issue(1); }

    int ba[2], sa2[2], bb[2], sb2[2];
#pragma unroll
    for (int tm = 0; tm < 2; tm++) {
        int r = wm * 32 + tm * 16 + (lane & 7) + ((lane >> 3) & 1) * 8;
        ba[tm] = r * 64; sa2[tm] = (r >> 1) & 3;
    }
#pragma unroll
    for (int tp = 0; tp < 2; tp++) {
        int r = wn * 32 + tp * 16 + (lane & 7) + (lane >> 4) * 8;
        bb[tp] = r * 64; sb2[tp] = (r >> 1) & 3;
    }
    const int qa = lane >> 4, qb = (lane >> 3) & 1;

    float acc[2][4][4];
#pragma unroll
    for (int i = 0; i < 2; i++)
#pragma unroll
        for (int j = 0; j < 4; j++)
#pragma unroll
            for (int r = 0; r < 4; r++) acc[i][j][r] = 0.f;

    for (int c = 0; c < NC; c++) {
        if (tid == 0 && c + 2 < NC) {
            const int cn = c + 2;
            if (cn >= 3)
                MBARRIER_WAIT_PARITY(mbE + (cn % 3) * 8, ((cn / 3) - 1) & 1);
            issue(cn);
        }
        MBARRIER_WAIT_PARITY(mbF + (c % 3) * 8, (c / 3) & 1);
        const uint32_t st = su + (uint32_t)(c % 3) * SSTG;
#pragma unroll
        for (int kk4 = 0; kk4 < 4; kk4++) {
            const uint32_t sub = (uint32_t)(kk4 >> 1) * 8192u;
            const int kk2 = kk4 & 1;
            uint32_t ah[2][4], al[2][4], bh[4][2], bl[4][2];
#pragma unroll
            for (int tm = 0; tm < 2; tm++) {
                const uint32_t ad = st + sub + ba[tm]
                    + (uint32_t)((((qa + kk2 * 2) ^ sa2[tm]) & 3) * 16);
                LDSM_X4(ah[tm][0], ah[tm][1], ah[tm][2], ah[tm][3], ad);
                LDSM_X4(al[tm][0], al[tm][1], al[tm][2], al[tm][3], ad + 16384u);
            }
#pragma unroll
            for (int tp = 0; tp < 2; tp++) {
                const uint32_t bd = st + 32768u + sub + bb[tp]
                    + (uint32_t)((((qb + kk2 * 2) ^ sb2[tp]) & 3) * 16);
                uint32_t r0, r1, r2, r3;
                LDSM_X4(r0, r1, r2, r3, bd);
                bh[2*tp][0] = r0; bh[2*tp][1] = r1;
                bh[2*tp+1][0] = r2; bh[2*tp+1][1] = r3;
                LDSM_X4(r0, r1, r2, r3, bd + 16384u);
                bl[2*tp][0] = r0; bl[2*tp][1] = r1;
                bl[2*tp+1][0] = r2; bl[2*tp+1][1] = r3;
            }
#pragma unroll
            for (int tm = 0; tm < 2; tm++)
#pragma unroll
                for (int tn = 0; tn < 4; tn++) {
                    MMA16(acc[tm][tn], ah[tm], bh[tn]);
                    MMA16(acc[tm][tn], ah[tm], bl[tn]);
                    MMA16(acc[tm][tn], al[tm], bh[tn]);
                }
        }
        if (lane == 0) MBARRIER_ARRIVE(mbE + (c % 3) * 8);
    }

#pragma unroll
    for (int tm = 0; tm < 2; tm++) {
        const int lr0 = wm * 32 + tm * 16 + (lane >> 2);
        const int r0 = m0 + lr0, r1 = r0 + 8;
#pragma unroll
        for (int tn = 0; tn < 4; tn++) {
            const int gn = n0 + wn * 32 + tn * 8 + (lane & 3) * 2;
            float v0 = acc[tm][tn][0], v1 = acc[tm][tn][1];
            float v2 = acc[tm][tn][2], v3 = acc[tm][tn][3];
            if (g.bias) {
                float b0 = g.bias[gn], b1 = g.bias[gn + 1];
                v0 += b0; v1 += b1; v2 += b0; v3 += b1;
            }
            if (g.act == 1) {
                v0 = tanhf(v0); v1 = tanhf(v1);
                v2 = tanhf(v2); v3 = tanhf(v3);
            }
            if (g.atomic) {
                atomicAdd(&g.C[(ll)r0 * 512 + gn], v0);
                atomicAdd(&g.C[(ll)r0 * 512 + gn + 1], v1);
                atomicAdd(&g.C[(ll)r1 * 512 + gn], v2);
                atomicAdd(&g.C[(ll)r1 * 512 + gn + 1], v3);
            } else {
                if (g.C) {
                    *(float2*)&g.C[(ll)r0 * 512 + gn] = make_float2(v0, v1);
                    *(float2*)&g.C[(ll)r1 * 512 + gn] = make_float2(v2, v3);
                }
                if (g.Ch) {
                    splitw2_t(g.Ch, g.Cl, r0, gn, g.okc, v0, v1);
                    splitw2_t(g.Ch, g.Cl, r1, gn, g.okc, v2, v3);
                }
            }
        }
    }
}

// ===================== producers ===========================================
__global__ __launch_bounds__(256)
void transpose_k(const float* __restrict__ know, __half* __restrict__ kh)
{
    __shared__ float t[32][65];
    const int b = blockIdx.z;
    const int n0 = blockIdx.x * 32, d0 = blockIdx.y * 64;
    const int tx = threadIdx.x, ty = threadIdx.y;
#pragma unroll
    for (int r = 0; r < 8; r++) {
        int dl = ty + r * 8;
        int n = n0 + tx;
        t[tx][dl] = (n < NHW) ? know[((ll)b * ND + d0 + dl) * NHW + n] : 0.f;
    }
    __syncthreads();
    const int tid = ty * 32 + tx;
    const int nl = tid & 31, dg = tid >> 5;
    if (n0 + nl < NHW) {
        float f[8];
#pragma unroll
        for (int i = 0; i < 8; i++) f[i] = t[nl][dg * 8 + i];
        hi8_t(kh, b * NHW + n0 + nl, d0 + dg * 8, 16, f);
    }
}

struct TDesc { const float* src; __half* dh; ll E; int R; int kc; };
struct TBatch { TDesc d[9]; };

__global__ __launch_bounds__(256)
void trans_w(TBatch tb)
{
    const TDesc td = tb.d[blockIdx.z];
    const int k0 = blockIdx.y * 64, n0 = blockIdx.x * 32;
    if (k0 >= td.R) return;
    __half* dl = td.dh + td.E;
    __shared__ float t[32][65];
    const int tx = threadIdx.x, ty = threadIdx.y;
#pragma unroll
    for (int r = 0; r < 8; r++) {
        int kk = ty + r * 8;
        t[tx][kk] = td.src[(ll)(k0 + kk) * 512 + n0 + tx];
    }
    __syncthreads();
    const int tid = ty * 32 + tx;
    const int nl = tid & 31, kg = tid >> 5;
    float f[8];
#pragma unroll
    for (int i = 0; i < 8; i++) f[i] = t[nl][kg * 8 + i];
    splitw8_t(td.dh, dl, n0 + nl, k0 + kg * 8, td.kc, f);
}

__global__ void init_bufs(const float* __restrict__ bwcat,
                          char* __restrict__ Sb, float* __restrict__ outM)
{
    int i = blockIdx.x * 256 + threadIdx.x;
    ((float*)(Sb + B_QF))[i] = 0.f;
    ((float*)(Sb + B_CQ))[i] = 0.f;
    if (i < NM) ((float*)(Sb + B_LOGIT))[i] = 0.f;
    if (i < 512) ((float*)(Sb + B_BIAS2))[i] = 0.f;
    outM[i] = bwcat[i & 511];
}

__global__ void tanhsplit_kernel(const float* __restrict__ qf,
                                 const float* __restrict__ bsc,
                                 __half* __restrict__ qh)
{
    int g = blockIdx.x * 256 + threadIdx.x;
    int row = g >> 6, k = (g & 63) * 8;
    float f[8];
#pragma unroll
    for (int i = 0; i < 8; i++)
        f[i] = tanhf(qf[(ll)row * 512 + k + i] + bsc[k + i]);
    splitw8_t(qh, qh + 131072, row, k, 16, f);
}

// split copies + wsumT + bias2 fused into one launch (grid 672)
__global__ void copy_split(const float* __restrict__ q, const float* __restrict__ c0,
                           const float* __restrict__ m0, const float* __restrict__ wc2,
                           const float* __restrict__ wk,
                           const float* __restrict__ Wwcat,
                           const float* __restrict__ Wc1,
                           const float* __restrict__ bk,
                           const float* __restrict__ bc1,
                           char* __restrict__ Sb)
{
    const int bx = blockIdx.x, tid = threadIdx.x;
    if (bx < 512) {
        int g = bx * 256 + tid;
        const float* src; __half* h; ll E; int ld, kc, j;
        if (g < 32768)       { src = q;   h = (__half*)(Sb + B_QR);   E = 262144; ld = 1024; kc = 32; j = g; }
        else if (g < 49152)  { src = c0;  h = (__half*)(Sb + B_C0R);  E = 131072; ld = 512;  kc = 16; j = g - 32768; }
        else if (g < 65536)  { src = m0;  h = (__half*)(Sb + B_M0R);  E = 131072; ld = 512;  kc = 16; j = g - 49152; }
        else if (g < 98304)  { src = wc2; h = (__half*)(Sb + B_WC2R); E = 262144; ld = 512;  kc = 16; j = g - 65536; }
        else                 { src = wk;  h = (__half*)(Sb + B_WKP);  E = 262144; ld = 512;  kc = 16; j = g - 98304; }
        const int gpr = ld >> 3;
        int row = j / gpr, k = (j % gpr) * 8;
        float f[8];
        const float* s = src + (ll)row * ld + k;
#pragma unroll
        for (int i = 0; i < 8; i++) f[i] = s[i];
        splitw8_t(h, h + E, row, k, kc, f);
    } else if (bx < 640) {
        // wsumT: nmBT chunks 16-31
        __half* nh = (__half*)(Sb + B_NMBT);
        int g = (bx - 512) * 256 + tid;
        int n = g >> 6, k = (g & 63) * 8;
        float f[8];
#pragma unroll
        for (int i = 0; i < 8; i++)
            f[i] = Wwcat[(ll)(512 + k + i) * 512 + n] + Wwcat[(ll)(1024 + k + i) * 512 + n];
        splitw8_t(nh, nh + 524288, n, 512 + k, 32, f);
    } else {
        // bias2: b2 += bc1 (e-block 0) + bk @ Wc1[D:2D] partials
        float* b2 = (float*)(Sb + B_BIAS2);
        int idx = bx - 640;              // 0..31
        int d = (idx & 1) * 256 + tid;
        int e0 = (idx >> 1) * 32;
        float acc = (e0 == 0) ? bc1[d] : 0.f;
#pragma unroll
        for (int e = 0; e < 32; e++)
            acc += bk[e0 + e] * Wc1[(ll)(512 + e0 + e) * 512 + d];
        atomicAdd(&b2[d], acc);
    }
}

// attnc fused with vsplit: control -> outC, v = control*war -> planes
__global__ __launch_bounds__(256)
void attnc_kernel(const float* __restrict__ words, const float* __restrict__ cq,
                  const float* __restrict__ bcq,
                  const float* __restrict__ wac, const float* __restrict__ bac,
                  const float* __restrict__ war,
                  float* __restrict__ control, __half* __restrict__ vh)
{
    const int b = blockIdx.x, tid = threadIdx.x;
    const int warp = tid >> 5, lane = tid & 31;
    __shared__ float cw[ND];
    __shared__ float sa[NS];
    for (int d = tid; d < ND; d += 256)
        cw[d] = (cq[(ll)b * ND + d] + bcq[d]) * wac[d];
    __syncthreads();
#pragma unroll
    for (int r = 0; r < 4; r++) {
        int s = warp * 4 + r;
        const float* wp = words + ((ll)b * NS + s) * ND;
        float acc = 0.f;
        for (int d = lane; d < ND; d += 32) acc += cw[d] * wp[d];
#pragma unroll
        for (int o = 16; o; o >>= 1) acc += __shfl_xor_sync(0xffffffffu, acc, o);
        if (lane == 0) sa[s] = acc + bac[0];
    }
    __syncthreads();
    if (warp == 0) {
        float v = sa[lane], mx = v;
#pragma unroll
        for (int o = 16; o; o >>= 1) mx = fmaxf(mx, __shfl_xor_sync(0xffffffffu, mx, o));
        float e = expf(v - mx), sm = e;
#pragma unroll
        for (int o = 16; o; o >>= 1) sm += __shfl_xor_sync(0xffffffffu, sm, o);
        sa[lane] = e / sm;
    }
    __syncthreads();
    for (int d = tid; d < ND; d += 256) {
        float acc = 0.f;
#pragma unroll 8
        for (int s = 0; s < NS; s++) acc += sa[s] * words[((ll)b * NS + s) * ND + d];
        control[(ll)b * ND + d] = acc;
        splitw_t(vh, vh + 131072, b, d, 16, acc * war[d]);
    }
}

// softmax over n fused with read: ar in smem, read -> split planes
__global__ __launch_bounds__(256)
void softread_kernel(const float* __restrict__ logit,
                     const float* __restrict__ know, __half* __restrict__ rh)
{
    const int b = blockIdx.x, tid = threadIdx.x;
    const int warp = tid >> 5, lane = tid & 31;
    __shared__ float s[256];
    __shared__ float ar[256];
    float v = (tid < NHW) ? logit[(ll)b * NHW + tid] : -1e30f;
    s[tid] = v; __syncthreads();
    for (int o = 128; o; o >>= 1) { if (tid < o) s[tid] = fmaxf(s[tid], s[tid + o]); __syncthreads(); }
    float mx = s[0]; __syncthreads();
    float e = (tid < NHW) ? expf(v - mx) : 0.f;
    s[tid] = e; __syncthreads();
    for (int o = 128; o; o >>= 1) { if (tid < o) s[tid] += s[tid + o]; __syncthreads(); }
    float sum = s[0];
    ar[tid] = e / sum;
    __syncthreads();
    for (int d = warp; d < ND; d += 8) {
        const float* kp = know + ((ll)b * ND + d) * NHW;
        float acc = 0.f;
        for (int n = lane; n < NHW; n += 32) acc += kp[n] * ar[n];
#pragma unroll
        for (int o = 16; o; o >>= 1) acc += __shfl_xor_sync(0xffffffffu, acc, o);
        if (lane == 0) splitw_t(rh, rh + 131072, b, d, 16, acc);
    }
}

// ===========================================================================
extern "C" void kernel_launch(void* const* d_in, const int* in_sizes, int n_in,
                              void* d_out, int out_size)
{
    const float* words    = (const float*)d_in[0];
    const float* question = (const float*)d_in[1];
    const float* know     = (const float*)d_in[2];
    const float* control0 = (const float*)d_in[3];
    const float* memory0  = (const float*)d_in[4];
    const float* Wsc  = (const float*)d_in[5];
    const float* bsc  = (const float*)d_in[6];
    const float* Wp   = (const float*)d_in[7];
    const float* bp   = (const float*)d_in[8];
    const float* Wcq  = (const float*)d_in[9];
    const float* bcq  = (const float*)d_in[10];
    const float* wac  = (const float*)d_in[11];
    const float* bac  = (const float*)d_in[12];
    const float* Wm   = (const float*)d_in[13];
    const float* bm   = (const float*)d_in[14];
    const float* Wk   = (const float*)d_in[15];
    const float* bk   = (const float*)d_in[16];
    const float* Wc1  = (const float*)d_in[17];
    const float* bc1  = (const float*)d_in[18];
    const float* Wc2  = (const float*)d_in[19];
    const float* war  = (const float*)d_in[21];
    const float* Wwcat = (const float*)d_in[27];
    const float* bwcat = (const float*)d_in[28];

    cudaFuncSetAttribute(tc_gemm<1>, cudaFuncAttributeMaxDynamicSharedMemorySize, SMH);
    cudaFuncSetAttribute(tc_gemm<2>, cudaFuncAttributeMaxDynamicSharedMemorySize, SMH);
    cudaFuncSetAttribute(tc_gemmb, cudaFuncAttributeMaxDynamicSharedMemorySize, SMB);

    char* Sb = nullptr;
    cudaGetSymbolAddress((void**)&Sb, g_s);

    float* outC = (float*)d_out;
    float* outM = (float*)d_out + (ll)NB * ND;

    auto F  = [&](ll off) { return (float*)(Sb + off); };
    auto Hh = [&](ll off) { return (__half*)(Sb + off); };
    Op KNOWT = { Hh(B_KNOWT), nullptr, 16 };
    Op SPK   = { Hh(B_SPK),   nullptr, 16 };
    Op WKT_H = { Hh(B_WKT),   nullptr, 16 };
    Op W1A_H = { Hh(B_W1AT),  nullptr, 16 };
    Op WKW_H = { Hh(B_WKWT),  nullptr, 16 };
    Op Z = { nullptr, nullptr, 0 };

    init_bufs<<<512, 256>>>(bwcat, Sb, outM);
    {
        TBatch tb;
        tb.d[0] = { Wk,                     Hh(B_WKT),   262144, 512, 16 };
        tb.d[1] = { Wc1,                    Hh(B_W1AT),  262144, 512, 16 };
        tb.d[2] = { Wc1 + (ll)ND * ND,      Hh(B_W1BT),  262144, 512, 16 };
        tb.d[3] = { Wsc,                    Hh(B_WSCT),  524288, 1024, 32 };
        tb.d[4] = { Wp,                     Hh(B_WPT),   262144, 512, 16 };
        tb.d[5] = { Wcq,                    Hh(B_WCQT),  524288, 1024, 32 };
        tb.d[6] = { Wm,                     Hh(B_WMT),   262144, 512, 16 };
        tb.d[7] = { Wc1 + (ll)2 * ND * ND,  Hh(B_WC1CT), 262144, 512, 16 };
        tb.d[8] = { Wwcat,                  Hh(B_NMBT),  524288, 512, 32 };
        trans_w<<<dim3(16, 16, 9), dim3(32, 8)>>>(tb);
    }
    transpose_k<<<dim3(7, 8, NB), dim3(32, 8)>>>(know, Hh(B_KNOWT));
    copy_split<<<672, 256>>>(question, control0, memory0, Wc2, Wk,
                             Wwcat, Wc1, bk, bc1, Sb);

    const ll CH16 = 16 * 4096;

    // batch1: q-half1, q-half2 (split-K atomic), pm, WkW1b
    {
        GDBatch b{};
        b.d[0] = { Hh(B_QR), Hh(B_QR) + 262144, 32,
                   Hh(B_WSCT), Hh(B_WSCT) + 524288, 32,
                   512, F(B_QF), nullptr, nullptr, 0, nullptr, 0, 1, 2 };
        b.d[1] = { Hh(B_QR) + CH16, Hh(B_QR) + 262144 + CH16, 32,
                   Hh(B_WSCT) + CH16, Hh(B_WSCT) + 524288 + CH16, 32,
                   512, F(B_QF), nullptr, nullptr, 0, nullptr, 0, 1, 2 };
        b.d[2] = { Hh(B_M0R), Hh(B_M0R) + 131072, 16,
                   Hh(B_WMT), Hh(B_WMT) + 262144, 16,
                   512, F(B_PMF), Hh(B_PMP), Hh(B_PMP) + 131072, 16, bm, 0, 0, 2 };
        b.d[3] = { Hh(B_W1BT), Hh(B_W1BT) + 262144, 16,
                   Hh(B_WKP), Hh(B_WKP) + 262144, 16,
                   512, nullptr, Hh(B_WKWT), Hh(B_WKWT) + 262144, 16,
                   nullptr, 0, 0, 4 };
        tc_gemmb<<<dim3(4, 4, 4), 512, SMB>>>(b);
    }

    // HEAVY 1: spk = (knowT_hi @ Wk_hi + bk) * pm[b] -> hi-plane
    tc_gemm<1><<<dim3(2, NM / 128), 512, SMH>>>(
        KNOWT, Z, WKT_H, Z, 512,
        Hh(B_SPK), 16, bk,
        F(B_PMF), nullptr, nullptr);

    tanhsplit_kernel<<<64, 256>>>(F(B_QF), bsc, Hh(B_Q));

    // batch2: pa, pmc
    {
        GDBatch b{};
        b.d[0] = { Hh(B_Q), Hh(B_Q) + 131072, 16,
                   Hh(B_WPT), Hh(B_WPT) + 262144, 16,
                   512, nullptr, Hh(B_PA), Hh(B_PA) + 131072, 16, bp, 0, 0, 2 };
        b.d[1] = { Hh(B_PMP), Hh(B_PMP) + 131072, 16,
                   Hh(B_WC1CT), Hh(B_WC1CT) + 262144, 16,
                   512, F(B_PMC), nullptr, nullptr, 0, F(B_BIAS2), 0, 0, 2 };
        tc_gemmb<<<dim3(4, 2, 2), 512, SMB>>>(b);
    }
    // cq split-K batch
    {
        GDBatch b{};
        b.d[0] = { Hh(B_C0R), Hh(B_C0R) + 131072, 16,
                   Hh(B_WCQT), Hh(B_WCQT) + 524288, 32,
                   512, F(B_CQ), nullptr, nullptr, 0, nullptr, 0, 1, 2 };
        b.d[1] = { Hh(B_PA), Hh(B_PA) + 131072, 16,
                   Hh(B_WCQT) + CH16, Hh(B_WCQT) + 524288 + CH16, 32,
                   512, F(B_CQ), nullptr, nullptr, 0, nullptr, 0, 1, 2 };
        tc_gemmb<<<dim3(4, 2, 2), 512, SMB>>>(b);
    }
    // control -> outC ; v = control*war -> planes (fused)
    attnc_kernel<<<NB, 256>>>(words, F(B_CQ), bcq, wac, bac, war,
                              outC, Hh(B_V));
    // u = v @ Wc2
    {
        GDBatch b{};
        b.d[0] = { Hh(B_V), Hh(B_V) + 131072, 16,
                   Hh(B_WC2R), Hh(B_WC2R) + 262144, 16,
                   512, F(B_U), nullptr, nullptr, 0, nullptr, 0, 0, 2 };
        tc_gemmb<<<dim3(4, 2, 1), 512, SMB>>>(b);
    }
    // HEAVY 2: logit += relu(spk_hi@W1a_hi + knowT_hi@WkW_hi + pmc).u
    tc_gemm<2><<<dim3(2, NM / 128), 512, SMH>>>(
        SPK, KNOWT, W1A_H, WKW_H, 1024,
        nullptr, 16, nullptr,
        F(B_PMC), F(B_U), F(B_LOGIT));

    // softmax + read fused
    softread_kernel<<<NB, 256>>>(F(B_LOGIT), know, Hh(B_READ));

    // next_mem split-K batch
    {
        GDBatch b{};
        b.d[0] = { Hh(B_READ), Hh(B_READ) + 131072, 16,
                   Hh(B_NMBT), Hh(B_NMBT) + 524288, 32,
                   512, outM, nullptr, nullptr, 0, nullptr, 0, 1, 2 };
        b.d[1] = { Hh(B_M0R), Hh(B_M0R) + 131072, 16,
                   Hh(B_NMBT) + CH16, Hh(B_NMBT) + 524288 + CH16, 32,
                   512, outM, nullptr, nullptr, 0, nullptr, 0, 1, 2 };
        tc_gemmb<<<dim3(4, 2, 2), 512, SMB>>>(b);
    }
}